// round 11
// baseline (speedup 1.0000x reference)
#include <cuda_runtime.h>
#include <cuda_bf16.h>
#include <cstdint>
#include <math.h>

#define DIMX  1024
#define GQ    256
#define QKD   128
#define HIDX  2048
#define NTOK  16384
#define NBG   64

// ---------------- scratch (device globals; no allocation) ----------------
__device__ float g_normed[(size_t)NTOK * DIMX];
__device__ float g_v    [(size_t)NTOK * HIDX];
__device__ float g_gate [(size_t)NTOK * HIDX];
__device__ float g_qksilu[(size_t)NTOK * QKD];
__device__ float g_qq   [(size_t)NTOK * QKD];
__device__ float g_lq   [(size_t)NTOK * QKD];
__device__ float g_qkT  [(size_t)NBG * QKD * GQ];
__device__ float g_lkT  [(size_t)NBG * QKD * GQ];
__device__ float g_attn [(size_t)NBG * GQ * GQ];
__device__ float g_linkv[(size_t)NBG * QKD * HIDX];
__device__ float g_linkvc[(size_t)NBG * QKD * HIDX];
__device__ float g_act  [(size_t)NTOK * HIDX];
__device__ float g_biastab[GQ];
// tf32-pre-rounded, K-major (transposed) weights
__device__ float g_WcatT[(size_t)(2 * HIDX + QKD) * DIMX];  // [4224][1024]: Wh rows then Wqk rows
__device__ float g_WoutT[(size_t)DIMX * HIDX];              // [1024][2048]

// ---------------- small helpers ----------------
__device__ __forceinline__ float silu_f(float x) { return x / (1.0f + expf(-x)); }

__device__ __forceinline__ float tfr(float f) {        // round fp32 -> tf32 (bits in fp32)
    uint32_t r;
    asm("cvt.rna.tf32.f32 %0, %1;" : "=r"(r) : "f"(f));
    return __uint_as_float(r);
}
__device__ __forceinline__ void mma_tf32(float (&d)[4], const uint32_t (&a)[4],
                                         uint32_t b0, uint32_t b1) {
    asm volatile(
        "mma.sync.aligned.m16n8k8.row.col.f32.tf32.tf32.f32 "
        "{%0,%1,%2,%3}, {%4,%5,%6,%7}, {%8,%9}, {%0,%1,%2,%3};\n"
        : "+f"(d[0]), "+f"(d[1]), "+f"(d[2]), "+f"(d[3])
        : "r"(a[0]), "r"(a[1]), "r"(a[2]), "r"(a[3]), "r"(b0), "r"(b1));
}

// ---------------- prep: T5 bias table ----------------
__global__ void prep_kernel(const float* __restrict__ rel_table) {
    int n = threadIdx.x;   // causal distance 0..255
    int bucket;
    if (n < 16) bucket = n;
    else {
        int v = 16 + (int)(logf((float)n / 16.0f) / logf(8.0f) * 16.0f);
        bucket = v < 31 ? v : 31;
    }
    g_biastab[n] = rel_table[bucket] * sqrtf(128.0f);
}

// ---------------- transpose + tf32 round: src[R][C] -> dst[C][R] ----------------
__global__ void transpose_kernel(const float* __restrict__ src, float* __restrict__ dst,
                                 int R, int C) {
    __shared__ float t[32][33];
    int c0 = blockIdx.x * 32, r0 = blockIdx.y * 32;
    int tx = threadIdx.x, ty = threadIdx.y;   // 32 x 8
    #pragma unroll
    for (int j = 0; j < 32; j += 8)
        t[ty + j][tx] = tfr(src[(size_t)(r0 + ty + j) * C + c0 + tx]);
    __syncthreads();
    #pragma unroll
    for (int j = 0; j < 32; j += 8)
        dst[(size_t)(c0 + ty + j) * R + r0 + tx] = t[tx][ty + j];
}

// ---------------- LayerNorm -> fp32 (tf32-rounded) ----------------
__global__ void ln_kernel(const float* __restrict__ x, const float* __restrict__ w,
                          const float* __restrict__ b) {
    int row = blockIdx.x, t = threadIdx.x;   // 256 threads, 4 floats each
    float4 f = reinterpret_cast<const float4*>(x + (size_t)row * DIMX)[t];
    float s  = f.x + f.y + f.z + f.w;
    float s2 = f.x*f.x + f.y*f.y + f.z*f.z + f.w*f.w;
    #pragma unroll
    for (int o = 16; o; o >>= 1) {
        s  += __shfl_xor_sync(0xffffffffu, s,  o);
        s2 += __shfl_xor_sync(0xffffffffu, s2, o);
    }
    __shared__ float ss[8], ss2[8], smu, sinv;
    if ((t & 31) == 0) { ss[t >> 5] = s; ss2[t >> 5] = s2; }
    __syncthreads();
    if (t == 0) {
        float S = 0.f, S2 = 0.f;
        #pragma unroll
        for (int k = 0; k < 8; k++) { S += ss[k]; S2 += ss2[k]; }
        float mu  = S * (1.0f / 1024.0f);
        float var = S2 * (1.0f / 1024.0f) - mu * mu;
        smu = mu; sinv = rsqrtf(var + 1e-5f);
    }
    __syncthreads();
    float mu = smu, inv = sinv;
    float4 wv = reinterpret_cast<const float4*>(w)[t];
    float4 bv = reinterpret_cast<const float4*>(b)[t];
    float4 o;
    o.x = tfr((f.x - mu)*inv*wv.x + bv.x);
    o.y = tfr((f.y - mu)*inv*wv.y + bv.y);
    o.z = tfr((f.z - mu)*inv*wv.z + bv.z);
    o.w = tfr((f.w - mu)*inv*wv.w + bv.w);
    reinterpret_cast<float4*>(g_normed + (size_t)row * DIMX)[t] = o;
}

// ---------------- head expand: coalesced smem transpose for k heads ----------
// grid (64 bg, 4 dtiles), block (32, 32)
__global__ void qkhead_kernel(const float* __restrict__ qk_w, const float* __restrict__ qk_b) {
    __shared__ float s2[32][33], s3[32][33];
    int bg = blockIdx.x, d0 = blockIdx.y * 32;
    int tx = threadIdx.x, ty = threadIdx.y;
    int d = d0 + tx;
    float w0 = qk_w[d],           b0 = qk_b[d];
    float w1 = qk_w[QKD + d],     b1 = qk_b[QKD + d];
    float w2 = qk_w[2*QKD + d],   b2 = qk_b[2*QKD + d];
    float w3 = qk_w[3*QKD + d],   b3 = qk_b[3*QKD + d];
    #pragma unroll 1
    for (int tc = 0; tc < 8; tc++) {
        int tok = tc * 32 + ty;
        size_t t = (size_t)bg * GQ + tok;
        float v = g_qksilu[t * QKD + d];
        g_qq[t * QKD + d] = tfr(v * w0 + b0);
        g_lq[t * QKD + d] = tfr(v * w1 + b1);
        s2[tx][ty] = tfr(v * w2 + b2);     // [d_local][tok_local]
        s3[tx][ty] = tfr(v * w3 + b3);
        __syncthreads();
        size_t o = (size_t)bg * QKD * GQ + (size_t)(d0 + ty) * GQ + tc * 32 + tx;
        g_qkT[o] = s2[ty][tx];
        g_lkT[o] = s3[ty][tx];
        __syncthreads();
    }
}

// ---------------- exclusive cumsum over groups ----------------
__global__ void cumsum_kernel() {
    int i  = blockIdx.x * 256 + threadIdx.x;
    int b  = i >> 18;
    int de = i & ((1 << 18) - 1);
    float a = 0.f;
    #pragma unroll
    for (int g = 0; g < 16; g++) {
        size_t off = ((size_t)(b * 16 + g) << 18) + de;
        g_linkvc[off] = tfr(a);
        a += g_linkv[off];
    }
}

#define ASTRIDE 40
#define BSTRIDE 132

// ================= weight GEMMs: 128x128 CTA, 64x64 warp tiles, 128 thr ======
// W=0: normed @ WcatT'  M=16384 N=4224 K=1024; n<2048->v(silu), <4096->gate(silu), else qksilu(silu)
// W=1: act @ WoutT'     M=16384 N=1024 K=2048; out = acc + bout + x
#define W_ABUF (128 * ASTRIDE)
#define W_SMEM (4 * W_ABUF * 4)

template<int W>
__global__ void __launch_bounds__(128) wgemm(const float* __restrict__ bias1,
                                             const float* __restrict__ bias2,
                                             const float* __restrict__ xres,
                                             float* __restrict__ out) {
    constexpr int K  = W ? 2048 : 1024;
    constexpr int KT = K / 32;
    const float* A = W ? g_act : g_normed;
    const float* B = W ? g_WoutT : g_WcatT;

    extern __shared__ float smem[];
    float* As = smem;                  // [2][128][ASTRIDE]
    float* Bs = smem + 2 * W_ABUF;     // [2][128][ASTRIDE]
    uint32_t sA = (uint32_t)__cvta_generic_to_shared(As);
    uint32_t sB = (uint32_t)__cvta_generic_to_shared(Bs);

    const int tid = threadIdx.x;
    const int m0 = blockIdx.x * 128, n0 = blockIdx.y * 128;
    const int warp = tid >> 5, lane = tid & 31;
    const int wm = warp >> 1, wn = warp & 1;           // 2x2 warps -> 64x64 each
    const int gid = lane >> 2, tig = lane & 3;
    const int lm = lane >> 2, ln = (lane & 3) << 1;

    float acc[4][8][4];
    #pragma unroll
    for (int a = 0; a < 4; a++)
        #pragma unroll
        for (int b = 0; b < 8; b++)
            #pragma unroll
            for (int c = 0; c < 4; c++) acc[a][b][c] = 0.f;

    auto load_tile = [&](int kt, int buf) {
        int k0 = kt * 32;
        const float* Ab = A + (size_t)m0 * K + k0;
        const float* Bb = B + (size_t)n0 * K + k0;
        #pragma unroll
        for (int it = 0; it < 8; it++) {
            int idx = tid + it * 128;
            int r = idx >> 3, kc = (idx & 7) << 2;
            uint32_t sa = sA + ((buf * 128 + r) * ASTRIDE + kc) * 4;
            asm volatile("cp.async.cg.shared.global [%0], [%1], 16;\n"
                         :: "r"(sa), "l"(Ab + (size_t)r * K + kc));
        }
        #pragma unroll
        for (int it = 0; it < 8; it++) {
            int idx = tid + it * 128;
            int r = idx >> 3, kc = (idx & 7) << 2;
            uint32_t sb = sB + ((buf * 128 + r) * ASTRIDE + kc) * 4;
            asm volatile("cp.async.cg.shared.global [%0], [%1], 16;\n"
                         :: "r"(sb), "l"(Bb + (size_t)r * K + kc));
        }
        asm volatile("cp.async.commit_group;\n");
    };

    load_tile(0, 0);
    for (int kt = 0; kt < KT; kt++) {
        int cur = kt & 1;
        if (kt + 1 < KT) {
            load_tile(kt + 1, cur ^ 1);
            asm volatile("cp.async.wait_group 1;\n");
        } else {
            asm volatile("cp.async.wait_group 0;\n");
        }
        __syncthreads();
        // k-permutation: logical frag slots {tig, tig+4} read physical cols {2tig, 2tig+1}
        #pragma unroll
        for (int ks = 0; ks < 32; ks += 8) {
            uint32_t af[4][4], bfr[8][2];
            #pragma unroll
            for (int mf = 0; mf < 4; mf++) {
                const float* ab = As + (cur * 128 + wm * 64 + mf * 16 + gid) * ASTRIDE + ks + 2 * tig;
                uint2 l0 = *reinterpret_cast<const uint2*>(ab);
                uint2 l1 = *reinterpret_cast<const uint2*>(ab + 8 * ASTRIDE);
                af[mf][0] = l0.x; af[mf][1] = l1.x; af[mf][2] = l0.y; af[mf][3] = l1.y;
            }
            #pragma unroll
            for (int nt = 0; nt < 8; nt++) {
                uint2 b2 = *reinterpret_cast<const uint2*>(
                    Bs + (cur * 128 + wn * 64 + nt * 8 + gid) * ASTRIDE + ks + 2 * tig);
                bfr[nt][0] = b2.x; bfr[nt][1] = b2.y;
            }
            #pragma unroll
            for (int mf = 0; mf < 4; mf++)
                #pragma unroll
                for (int nf = 0; nf < 8; nf++)
                    mma_tf32(acc[mf][nf], af[mf], bfr[nf][0], bfr[nf][1]);
        }
        __syncthreads();
    }

    // -------- epilogue --------
    #pragma unroll
    for (int mf = 0; mf < 4; mf++)
    #pragma unroll
    for (int nf = 0; nf < 8; nf++)
    #pragma unroll
    for (int h = 0; h < 2; h++) {
        int m = m0 + wm * 64 + mf * 16 + lm + h * 8;
        int n = n0 + wn * 64 + nf * 8 + ln;
        float v0 = acc[mf][nf][h * 2 + 0];
        float v1 = acc[mf][nf][h * 2 + 1];
        if constexpr (W == 0) {
            float b0 = (n < 4096) ? bias1[n] : bias2[n - 4096];
            float b1 = (n < 4096) ? bias1[n + 1] : bias2[n - 4095];
            float h0 = silu_f(v0 + b0);
            float h1 = silu_f(v1 + b1);
            if (n < HIDX)
                *reinterpret_cast<float2*>(g_v + (size_t)m * HIDX + n)
                    = make_float2(tfr(h0), tfr(h1));
            else if (n < 2 * HIDX)
                *reinterpret_cast<float2*>(g_gate + (size_t)m * HIDX + (n - HIDX))
                    = make_float2(h0, h1);
            else
                *reinterpret_cast<float2*>(g_qksilu + (size_t)m * QKD + (n - 2 * HIDX))
                    = make_float2(h0, h1);
        } else {
            size_t off = (size_t)m * DIMX + n;
            float2 xr = *reinterpret_cast<const float2*>(xres + off);
            *reinterpret_cast<float2*>(out + off)
                = make_float2(v0 + bias1[n] + xr.x, v1 + bias1[n + 1] + xr.y);
        }
    }
}

// ================= attention GEMM helpers =================
template<int MODE>
__device__ __forceinline__ const float* a_ptr(int bg, int m, int k) {
    if constexpr (MODE == 2) return g_qq + ((size_t)bg * GQ + m) * QKD + k;
    else if constexpr (MODE == 3) return g_lkT + (size_t)bg * QKD * GQ + (size_t)m * GQ + k;
    else {
        if (k < GQ) return g_attn + (size_t)bg * GQ * GQ + (size_t)m * GQ + k;
        else        return g_lq + ((size_t)bg * GQ + m) * QKD + (k - GQ);
    }
}
template<int MODE>
__device__ __forceinline__ const float* bnm_ptr(int bg, int k, int n) {
    if constexpr (MODE == 2) return g_qkT + (size_t)bg * QKD * GQ + (size_t)k * GQ + n;
    else if constexpr (MODE == 3) return g_v + ((size_t)bg * GQ + k) * HIDX + n;
    else {
        if (k < GQ) return g_v + ((size_t)bg * GQ + k) * HIDX + n;
        else        return g_linkvc + (size_t)bg * QKD * HIDX + (size_t)(k - GQ) * HIDX + n;
    }
}

// ======= mode 2 (sim/relu^2/mask): 256 thr, 32x64 warp tiles (unchanged) =====
#define A_BUF   (128 * ASTRIDE)
#define B_BUF_N (32 * BSTRIDE)
#define SMEMB_N ((2 * A_BUF + 2 * B_BUF_N) * 4)

__global__ void __launch_bounds__(256) sim_kernel() {
    constexpr int K  = 128;
    constexpr int KT = K / 32;
    extern __shared__ float smem[];
    float* As = smem;                 // [2][128][ASTRIDE]
    float* Bs = smem + 2 * A_BUF;     // [2][32][BSTRIDE]

    const int tid = threadIdx.x;
    int t = blockIdx.x;               // lower-triangular blocks: (0,0),(1,0),(1,1)
    int bx = (t + 1) >> 1;
    int by = t >> 1;
    const int m0 = bx * 128;
    const int n0 = by * 128;
    const int bg = blockIdx.z;
    const int warp = tid >> 5, lane = tid & 31;
    const int wm = warp & 3, wn = warp >> 2;
    const int gid = lane >> 2, tig = lane & 3;
    const int lm = lane >> 2, ln = (lane & 3) << 1;

    uint32_t sA = (uint32_t)__cvta_generic_to_shared(As);
    uint32_t sB = (uint32_t)__cvta_generic_to_shared(Bs);

    float acc[2][8][4];
    #pragma unroll
    for (int a = 0; a < 2; a++)
        #pragma unroll
        for (int b = 0; b < 8; b++)
            #pragma unroll
            for (int c = 0; c < 4; c++) acc[a][b][c] = 0.f;

    auto load_tile = [&](int kt, int buf) {
        int k0 = kt * 32;
        #pragma unroll
        for (int it = 0; it < 4; it++) {
            int idx = tid + it * 256;
            int r = idx >> 3, kc = (idx & 7) << 2;
            const float* gp = a_ptr<2>(bg, m0 + r, k0 + kc);
            uint32_t sa = sA + ((buf * 128 + r) * ASTRIDE + kc) * 4;
            asm volatile("cp.async.cg.shared.global [%0], [%1], 16;\n" :: "r"(sa), "l"(gp));
        }
        #pragma unroll
        for (int it = 0; it < 4; it++) {
            int idx = tid + it * 256;
            int r = idx >> 5, nc = (idx & 31) << 2;
            const float* gp = bnm_ptr<2>(bg, k0 + r, n0 + nc);
            uint32_t sb = sB + ((buf * 32 + r) * BSTRIDE + nc) * 4;
            asm volatile("cp.async.cg.shared.global [%0], [%1], 16;\n" :: "r"(sb), "l"(gp));
        }
        asm volatile("cp.async.commit_group;\n");
    };

    load_tile(0, 0);
    for (int kt = 0; kt < KT; kt++) {
        int cur = kt & 1;
        if (kt + 1 < KT) {
            load_tile(kt + 1, cur ^ 1);
            asm volatile("cp.async.wait_group 1;\n");
        } else {
            asm volatile("cp.async.wait_group 0;\n");
        }
        __syncthreads();
        #pragma unroll
        for (int ks = 0; ks < 32; ks += 8) {
            uint32_t af[2][4], bfr[8][2];
            #pragma unroll
            for (int mf = 0; mf < 2; mf++) {
                const float* ab = As + (cur * 128 + wm * 32 + mf * 16 + gid) * ASTRIDE + ks + 2 * tig;
                uint2 l0 = *reinterpret_cast<const uint2*>(ab);
                uint2 l1 = *reinterpret_cast<const uint2*>(ab + 8 * ASTRIDE);
                af[mf][0] = l0.x; af[mf][1] = l1.x; af[mf][2] = l0.y; af[mf][3] = l1.y;
            }
            #pragma unroll
            for (int nt = 0; nt < 8; nt++) {
                const uint32_t* bb = reinterpret_cast<const uint32_t*>(
                    Bs + (cur * 32 + ks + 2 * tig) * BSTRIDE + wn * 64 + nt * 8 + gid);
                bfr[nt][0] = bb[0];
                bfr[nt][1] = bb[BSTRIDE];
            }
            #pragma unroll
            for (int mf = 0; mf < 2; mf++)
                #pragma unroll
                for (int nf = 0; nf < 8; nf++)
                    mma_tf32(acc[mf][nf], af[mf], bfr[nf][0], bfr[nf][1]);
        }
        __syncthreads();
    }

    #pragma unroll
    for (int mf = 0; mf < 2; mf++)
    #pragma unroll
    for (int nf = 0; nf < 8; nf++)
    #pragma unroll
    for (int h = 0; h < 2; h++) {
        int m = m0 + wm * 32 + mf * 16 + lm + h * 8;
        int n = n0 + wn * 64 + nf * 8 + ln;
        float v0 = acc[mf][nf][h * 2 + 0];
        float v1 = acc[mf][nf][h * 2 + 1];
        float a0 = 0.f, a1 = 0.f;
        if (n <= m)     { float s = v0 * (1.f/256.f) + g_biastab[m - n];     s = fmaxf(s, 0.f); a0 = s * s; }
        if (n + 1 <= m) { float s = v1 * (1.f/256.f) + g_biastab[m - n - 1]; s = fmaxf(s, 0.f); a1 = s * s; }
        *reinterpret_cast<float2*>(g_attn + (size_t)bg * GQ * GQ + (size_t)m * GQ + n)
            = make_float2(tfr(a0), tfr(a1));
    }
}

// ======= modes 3/4: 128 thr, 64x64 warp tiles ===============================
// MODE 3: linkv = lkT@v /256                      M=128b  N=2048 K=256
// MODE 4: [attn|lq]@[v;linkvc], * gate -> act     M=256b  N=2048 K=384
#define ASMEM ((2 * A_BUF + 2 * B_BUF_N) * 4)

template<int MODE>
__global__ void __launch_bounds__(128) agemm() {
    constexpr int K  = (MODE == 3) ? 256 : 384;
    constexpr int KT = K / 32;
    extern __shared__ float smem[];
    float* As = smem;                 // [2][128][ASTRIDE]
    float* Bs = smem + 2 * A_BUF;     // [2][32][BSTRIDE]

    const int tid = threadIdx.x;
    const int m0 = blockIdx.x * 128;
    const int n0 = blockIdx.y * 128;
    const int bg = blockIdx.z;
    const int warp = tid >> 5, lane = tid & 31;
    const int wm = warp >> 1, wn = warp & 1;           // 2x2 warps -> 64x64 each
    const int gid = lane >> 2, tig = lane & 3;
    const int lm = lane >> 2, ln = (lane & 3) << 1;

    uint32_t sA = (uint32_t)__cvta_generic_to_shared(As);
    uint32_t sB = (uint32_t)__cvta_generic_to_shared(Bs);

    float acc[4][8][4];
    #pragma unroll
    for (int a = 0; a < 4; a++)
        #pragma unroll
        for (int b = 0; b < 8; b++)
            #pragma unroll
            for (int c = 0; c < 4; c++) acc[a][b][c] = 0.f;

    auto load_tile = [&](int kt, int buf) {
        int k0 = kt * 32;
        #pragma unroll
        for (int it = 0; it < 8; it++) {
            int idx = tid + it * 128;
            int r = idx >> 3, kc = (idx & 7) << 2;
            const float* gp = a_ptr<MODE>(bg, m0 + r, k0 + kc);
            uint32_t sa = sA + ((buf * 128 + r) * ASTRIDE + kc) * 4;
            asm volatile("cp.async.cg.shared.global [%0], [%1], 16;\n" :: "r"(sa), "l"(gp));
        }
        #pragma unroll
        for (int it = 0; it < 8; it++) {
            int idx = tid + it * 128;
            int r = idx >> 5, nc = (idx & 31) << 2;
            const float* gp = bnm_ptr<MODE>(bg, k0 + r, n0 + nc);
            uint32_t sb = sB + ((buf * 32 + r) * BSTRIDE + nc) * 4;
            asm volatile("cp.async.cg.shared.global [%0], [%1], 16;\n" :: "r"(sb), "l"(gp));
        }
        asm volatile("cp.async.commit_group;\n");
    };

    load_tile(0, 0);
    for (int kt = 0; kt < KT; kt++) {
        int cur = kt & 1;
        if (kt + 1 < KT) {
            load_tile(kt + 1, cur ^ 1);
            asm volatile("cp.async.wait_group 1;\n");
        } else {
            asm volatile("cp.async.wait_group 0;\n");
        }
        __syncthreads();
        #pragma unroll
        for (int ks = 0; ks < 32; ks += 8) {
            uint32_t af[4][4], bfr[8][2];
            #pragma unroll
            for (int mf = 0; mf < 4; mf++) {
                const float* ab = As + (cur * 128 + wm * 64 + mf * 16 + gid) * ASTRIDE + ks + 2 * tig;
                uint2 l0 = *reinterpret_cast<const uint2*>(ab);
                uint2 l1 = *reinterpret_cast<const uint2*>(ab + 8 * ASTRIDE);
                af[mf][0] = l0.x; af[mf][1] = l1.x; af[mf][2] = l0.y; af[mf][3] = l1.y;
            }
            #pragma unroll
            for (int nt = 0; nt < 8; nt++) {
                const uint32_t* bb = reinterpret_cast<const uint32_t*>(
                    Bs + (cur * 32 + ks + 2 * tig) * BSTRIDE + wn * 64 + nt * 8 + gid);
                bfr[nt][0] = bb[0];
                bfr[nt][1] = bb[BSTRIDE];
            }
            #pragma unroll
            for (int mf = 0; mf < 4; mf++)
                #pragma unroll
                for (int nf = 0; nf < 8; nf++)
                    mma_tf32(acc[mf][nf], af[mf], bfr[nf][0], bfr[nf][1]);
        }
        __syncthreads();
    }

    #pragma unroll
    for (int mf = 0; mf < 4; mf++)
    #pragma unroll
    for (int nf = 0; nf < 8; nf++)
    #pragma unroll
    for (int h = 0; h < 2; h++) {
        int m = m0 + wm * 64 + mf * 16 + lm + h * 8;
        int n = n0 + wn * 64 + nf * 8 + ln;
        float v0 = acc[mf][nf][h * 2 + 0];
        float v1 = acc[mf][nf][h * 2 + 1];
        if constexpr (MODE == 3) {
            *reinterpret_cast<float2*>(g_linkv + (size_t)bg * QKD * HIDX + (size_t)m * HIDX + n)
                = make_float2(v0 * (1.f/256.f), v1 * (1.f/256.f));
        } else {
            size_t row = (size_t)(bg * GQ + m);
            float2 gt = *reinterpret_cast<const float2*>(g_gate + row * HIDX + n);
            *reinterpret_cast<float2*>(g_act + row * HIDX + n)
                = make_float2(tfr(v0 * gt.x), tfr(v1 * gt.y));
        }
    }
}

// ---------------- host launcher ----------------
extern "C" void kernel_launch(void* const* d_in, const int* in_sizes, int n_in,
                              void* d_out, int out_size) {
    const float* x         = (const float*)d_in[0];
    const float* ln_w      = (const float*)d_in[1];
    const float* ln_b      = (const float*)d_in[2];
    const float* Wh        = (const float*)d_in[3];
    const float* bh        = (const float*)d_in[4];
    const float* Wqk       = (const float*)d_in[5];
    const float* bqk       = (const float*)d_in[6];
    const float* qk_w      = (const float*)d_in[7];
    const float* qk_b      = (const float*)d_in[8];
    const float* rel_table = (const float*)d_in[9];
    const float* Wout      = (const float*)d_in[10];
    const float* bout      = (const float*)d_in[11];
    float* out = (float*)d_out;

    cudaFuncSetAttribute(wgemm<0>, cudaFuncAttributeMaxDynamicSharedMemorySize, W_SMEM);
    cudaFuncSetAttribute(wgemm<1>, cudaFuncAttributeMaxDynamicSharedMemorySize, W_SMEM);
    cudaFuncSetAttribute(sim_kernel, cudaFuncAttributeMaxDynamicSharedMemorySize, SMEMB_N);
    cudaFuncSetAttribute(agemm<3>, cudaFuncAttributeMaxDynamicSharedMemorySize, ASMEM);
    cudaFuncSetAttribute(agemm<4>, cudaFuncAttributeMaxDynamicSharedMemorySize, ASMEM);

    float* WcatT_p; cudaGetSymbolAddress((void**)&WcatT_p, g_WcatT);
    float* WoutT_p; cudaGetSymbolAddress((void**)&WoutT_p, g_WoutT);

    prep_kernel<<<1, 256>>>(rel_table);
    transpose_kernel<<<dim3(128, 32), dim3(32, 8)>>>(Wh,   WcatT_p,                DIMX, 2 * HIDX);
    transpose_kernel<<<dim3(4, 32),   dim3(32, 8)>>>(Wqk,  WcatT_p + (size_t)4096 * DIMX, DIMX, QKD);
    transpose_kernel<<<dim3(32, 64),  dim3(32, 8)>>>(Wout, WoutT_p,                HIDX, DIMX);
    ln_kernel<<<NTOK, 256>>>(x, ln_w, ln_b);
    wgemm<0><<<dim3(128, 33), 128, W_SMEM>>>(bh, bqk, nullptr, nullptr);
    qkhead_kernel<<<dim3(64, 4), dim3(32, 32)>>>(qk_w, qk_b);
    sim_kernel<<<dim3(3, 1, 64),  256, SMEMB_N>>>();
    agemm<3><<<dim3(1, 16, 64), 128, ASMEM>>>();
    cumsum_kernel<<<4096, 256>>>();
    agemm<4><<<dim3(2, 16, 64), 128, ASMEM>>>();
    wgemm<1><<<dim3(128, 8), 128, W_SMEM>>>(bout, nullptr, x, out);
}

// round 12
// speedup vs baseline: 1.5685x; 1.5685x over previous
#include <cuda_runtime.h>
#include <cuda_fp16.h>
#include <cstdint>
#include <math.h>

#define DIMX  1024
#define GQ    256
#define QKD   128
#define HIDX  2048
#define NTOK  16384
#define NBG   64

// ---------------- scratch (device globals; no allocation) ----------------
__device__ __half g_normedh[(size_t)NTOK * DIMX];
__device__ float  g_v    [(size_t)NTOK * HIDX];
__device__ float  g_gate [(size_t)NTOK * HIDX];
__device__ float  g_qksilu[(size_t)NTOK * QKD];
__device__ float  g_qq   [(size_t)NTOK * QKD];
__device__ float  g_lq   [(size_t)NTOK * QKD];
__device__ float  g_qkT  [(size_t)NBG * QKD * GQ];
__device__ float  g_lkT  [(size_t)NBG * QKD * GQ];
__device__ float  g_attn [(size_t)NBG * GQ * GQ];
__device__ float  g_linkv[(size_t)NBG * QKD * HIDX];
__device__ float  g_linkvc[(size_t)NBG * QKD * HIDX];
__device__ __half g_acth [(size_t)NTOK * HIDX];
__device__ float  g_biastab[GQ];
// fp16, K-major (transposed) weights
__device__ __half g_WcatTh[(size_t)(2 * HIDX + QKD) * DIMX];  // [4224][1024]
__device__ __half g_WoutTh[(size_t)DIMX * HIDX];              // [1024][2048]

// ---------------- small helpers ----------------
__device__ __forceinline__ float silu_f(float x) { return x / (1.0f + expf(-x)); }

__device__ __forceinline__ float tfr(float f) {        // round fp32 -> tf32 (bits in fp32)
    uint32_t r;
    asm("cvt.rna.tf32.f32 %0, %1;" : "=r"(r) : "f"(f));
    return __uint_as_float(r);
}
__device__ __forceinline__ void mma_tf32(float (&d)[4], const uint32_t (&a)[4],
                                         uint32_t b0, uint32_t b1) {
    asm volatile(
        "mma.sync.aligned.m16n8k8.row.col.f32.tf32.tf32.f32 "
        "{%0,%1,%2,%3}, {%4,%5,%6,%7}, {%8,%9}, {%0,%1,%2,%3};\n"
        : "+f"(d[0]), "+f"(d[1]), "+f"(d[2]), "+f"(d[3])
        : "r"(a[0]), "r"(a[1]), "r"(a[2]), "r"(a[3]), "r"(b0), "r"(b1));
}
__device__ __forceinline__ void mma_f16(float (&d)[4], const uint32_t (&a)[4],
                                        uint32_t b0, uint32_t b1) {
    asm volatile(
        "mma.sync.aligned.m16n8k16.row.col.f32.f16.f16.f32 "
        "{%0,%1,%2,%3}, {%4,%5,%6,%7}, {%8,%9}, {%0,%1,%2,%3};\n"
        : "+f"(d[0]), "+f"(d[1]), "+f"(d[2]), "+f"(d[3])
        : "r"(a[0]), "r"(a[1]), "r"(a[2]), "r"(a[3]), "r"(b0), "r"(b1));
}

// ---------------- prep: T5 bias table ----------------
__global__ void prep_kernel(const float* __restrict__ rel_table) {
    int n = threadIdx.x;   // causal distance 0..255
    int bucket;
    if (n < 16) bucket = n;
    else {
        int v = 16 + (int)(logf((float)n / 16.0f) / logf(8.0f) * 16.0f);
        bucket = v < 31 ? v : 31;
    }
    g_biastab[n] = rel_table[bucket] * sqrtf(128.0f);
}

// ---------------- transpose + fp16 round: src[R][C] -> dst[C][R] ----------------
__global__ void transpose_kernel(const float* __restrict__ src, __half* __restrict__ dst,
                                 int R, int C) {
    __shared__ float t[32][33];
    int c0 = blockIdx.x * 32, r0 = blockIdx.y * 32;
    int tx = threadIdx.x, ty = threadIdx.y;   // 32 x 8
    #pragma unroll
    for (int j = 0; j < 32; j += 8)
        t[ty + j][tx] = src[(size_t)(r0 + ty + j) * C + c0 + tx];
    __syncthreads();
    #pragma unroll
    for (int j = 0; j < 32; j += 8)
        dst[(size_t)(c0 + ty + j) * R + r0 + tx] = __float2half_rn(t[tx][ty + j]);
}

// ---------------- LayerNorm -> fp16 ----------------
__global__ void ln_kernel(const float* __restrict__ x, const float* __restrict__ w,
                          const float* __restrict__ b) {
    int row = blockIdx.x, t = threadIdx.x;   // 256 threads, 4 floats each
    float4 f = reinterpret_cast<const float4*>(x + (size_t)row * DIMX)[t];
    float s  = f.x + f.y + f.z + f.w;
    float s2 = f.x*f.x + f.y*f.y + f.z*f.z + f.w*f.w;
    #pragma unroll
    for (int o = 16; o; o >>= 1) {
        s  += __shfl_xor_sync(0xffffffffu, s,  o);
        s2 += __shfl_xor_sync(0xffffffffu, s2, o);
    }
    __shared__ float ss[8], ss2[8], smu, sinv;
    if ((t & 31) == 0) { ss[t >> 5] = s; ss2[t >> 5] = s2; }
    __syncthreads();
    if (t == 0) {
        float S = 0.f, S2 = 0.f;
        #pragma unroll
        for (int k = 0; k < 8; k++) { S += ss[k]; S2 += ss2[k]; }
        float mu  = S * (1.0f / 1024.0f);
        float var = S2 * (1.0f / 1024.0f) - mu * mu;
        smu = mu; sinv = rsqrtf(var + 1e-5f);
    }
    __syncthreads();
    float mu = smu, inv = sinv;
    float4 wv = reinterpret_cast<const float4*>(w)[t];
    float4 bv = reinterpret_cast<const float4*>(b)[t];
    __half2* o2 = reinterpret_cast<__half2*>(g_normedh + (size_t)row * DIMX + t * 4);
    o2[0] = __floats2half2_rn((f.x - mu)*inv*wv.x + bv.x, (f.y - mu)*inv*wv.y + bv.y);
    o2[1] = __floats2half2_rn((f.z - mu)*inv*wv.z + bv.z, (f.w - mu)*inv*wv.w + bv.w);
}

// ---------------- head expand: coalesced smem transpose for k heads ----------
__global__ void qkhead_kernel(const float* __restrict__ qk_w, const float* __restrict__ qk_b) {
    __shared__ float s2[32][33], s3[32][33];
    int bg = blockIdx.x, d0 = blockIdx.y * 32;
    int tx = threadIdx.x, ty = threadIdx.y;
    int d = d0 + tx;
    float w0 = qk_w[d],           b0 = qk_b[d];
    float w1 = qk_w[QKD + d],     b1 = qk_b[QKD + d];
    float w2 = qk_w[2*QKD + d],   b2 = qk_b[2*QKD + d];
    float w3 = qk_w[3*QKD + d],   b3 = qk_b[3*QKD + d];
    #pragma unroll 1
    for (int tc = 0; tc < 8; tc++) {
        int tok = tc * 32 + ty;
        size_t t = (size_t)bg * GQ + tok;
        float v = g_qksilu[t * QKD + d];
        g_qq[t * QKD + d] = tfr(v * w0 + b0);
        g_lq[t * QKD + d] = tfr(v * w1 + b1);
        s2[tx][ty] = tfr(v * w2 + b2);
        s3[tx][ty] = tfr(v * w3 + b3);
        __syncthreads();
        size_t o = (size_t)bg * QKD * GQ + (size_t)(d0 + ty) * GQ + tc * 32 + tx;
        g_qkT[o] = s2[ty][tx];
        g_lkT[o] = s3[ty][tx];
        __syncthreads();
    }
}

// ---------------- exclusive cumsum over groups ----------------
__global__ void cumsum_kernel() {
    int i  = blockIdx.x * 256 + threadIdx.x;
    int b  = i >> 18;
    int de = i & ((1 << 18) - 1);
    float a = 0.f;
    #pragma unroll
    for (int g = 0; g < 16; g++) {
        size_t off = ((size_t)(b * 16 + g) << 18) + de;
        g_linkvc[off] = tfr(a);
        a += g_linkv[off];
    }
}

#define ASTRIDE 40
#define BSTRIDE 132
#define HSTR    80      // half stride (160B rows, same geometry as fp32 ASTRIDE)

// ================= fp16 weight GEMMs: 128x128 CTA, 64x64 warp tiles, 128 thr =
// W=0: normedh @ WcatTh'  M=16384 N=4224 K=1024
// W=1: acth @ WoutTh'     M=16384 N=1024 K=2048
#define WH_BUF  (128 * HSTR)                 // halves per tile buffer
#define W_SMEM  (4 * WH_BUF * 2)             // A+B, double buffered, bytes

template<int W>
__global__ void __launch_bounds__(128) wgemm(const float* __restrict__ bias1,
                                             const float* __restrict__ bias2,
                                             const float* __restrict__ xres,
                                             float* __restrict__ out) {
    constexpr int K  = W ? 2048 : 1024;
    constexpr int KT = K / 64;
    const __half* A = W ? g_acth : g_normedh;
    const __half* B = W ? g_WoutTh : g_WcatTh;

    extern __shared__ __half smemh[];
    __half* As = smemh;                  // [2][128][HSTR]
    __half* Bs = smemh + 2 * WH_BUF;     // [2][128][HSTR]
    uint32_t sA = (uint32_t)__cvta_generic_to_shared(As);
    uint32_t sB = (uint32_t)__cvta_generic_to_shared(Bs);

    const int tid = threadIdx.x;
    const int m0 = blockIdx.x * 128, n0 = blockIdx.y * 128;
    const int warp = tid >> 5, lane = tid & 31;
    const int wm = warp >> 1, wn = warp & 1;           // 2x2 warps -> 64x64 each
    const int gid = lane >> 2, tig = lane & 3;
    const int lm = lane >> 2, ln = (lane & 3) << 1;

    float acc[4][8][4];
    #pragma unroll
    for (int a = 0; a < 4; a++)
        #pragma unroll
        for (int b = 0; b < 8; b++)
            #pragma unroll
            for (int c = 0; c < 4; c++) acc[a][b][c] = 0.f;

    auto load_tile = [&](int kt, int buf) {
        int k0 = kt * 64;
        const __half* Ab = A + (size_t)m0 * K + k0;
        const __half* Bb = B + (size_t)n0 * K + k0;
        #pragma unroll
        for (int it = 0; it < 8; it++) {           // 128 rows x 64 halfs (8x16B per row)
            int idx = tid + it * 128;
            int r = idx >> 3, c = (idx & 7) << 3;  // c in halves
            uint32_t sa = sA + ((buf * 128 + r) * HSTR + c) * 2;
            asm volatile("cp.async.cg.shared.global [%0], [%1], 16;\n"
                         :: "r"(sa), "l"(Ab + (size_t)r * K + c));
        }
        #pragma unroll
        for (int it = 0; it < 8; it++) {
            int idx = tid + it * 128;
            int r = idx >> 3, c = (idx & 7) << 3;
            uint32_t sb = sB + ((buf * 128 + r) * HSTR + c) * 2;
            asm volatile("cp.async.cg.shared.global [%0], [%1], 16;\n"
                         :: "r"(sb), "l"(Bb + (size_t)r * K + c));
        }
        asm volatile("cp.async.commit_group;\n");
    };

    load_tile(0, 0);
    for (int kt = 0; kt < KT; kt++) {
        int cur = kt & 1;
        if (kt + 1 < KT) {
            load_tile(kt + 1, cur ^ 1);
            asm volatile("cp.async.wait_group 1;\n");
        } else {
            asm volatile("cp.async.wait_group 0;\n");
        }
        __syncthreads();
        // k16-permutation: logical k {2t,2t+1,2t+8,2t+9} -> phys {4t..4t+3}
        #pragma unroll
        for (int ks = 0; ks < 4; ks++) {           // 4 k16 blocks per 64-half stage
            uint32_t af[4][4], bfr[8][2];
            #pragma unroll
            for (int mf = 0; mf < 4; mf++) {
                const __half* ab = As + (size_t)(cur * 128 + wm * 64 + mf * 16 + gid) * HSTR
                                   + ks * 16 + 4 * tig;
                uint2 l0 = *reinterpret_cast<const uint2*>(ab);
                uint2 l1 = *reinterpret_cast<const uint2*>(ab + 8 * HSTR);
                af[mf][0] = l0.x; af[mf][1] = l1.x; af[mf][2] = l0.y; af[mf][3] = l1.y;
            }
            #pragma unroll
            for (int nt = 0; nt < 8; nt++) {
                const __half* bb = Bs + (size_t)(cur * 128 + wn * 64 + nt * 8 + gid) * HSTR
                                   + ks * 16 + 4 * tig;
                uint2 b2 = *reinterpret_cast<const uint2*>(bb);
                bfr[nt][0] = b2.x; bfr[nt][1] = b2.y;
            }
            #pragma unroll
            for (int mf = 0; mf < 4; mf++)
                #pragma unroll
                for (int nf = 0; nf < 8; nf++)
                    mma_f16(acc[mf][nf], af[mf], bfr[nf][0], bfr[nf][1]);
        }
        __syncthreads();
    }

    // -------- epilogue --------
    #pragma unroll
    for (int mf = 0; mf < 4; mf++)
    #pragma unroll
    for (int nf = 0; nf < 8; nf++)
    #pragma unroll
    for (int h = 0; h < 2; h++) {
        int m = m0 + wm * 64 + mf * 16 + lm + h * 8;
        int n = n0 + wn * 64 + nf * 8 + ln;
        float v0 = acc[mf][nf][h * 2 + 0];
        float v1 = acc[mf][nf][h * 2 + 1];
        if constexpr (W == 0) {
            float b0 = (n < 4096) ? bias1[n] : bias2[n - 4096];
            float b1 = (n < 4096) ? bias1[n + 1] : bias2[n - 4095];
            float h0 = silu_f(v0 + b0);
            float h1 = silu_f(v1 + b1);
            if (n < HIDX)
                *reinterpret_cast<float2*>(g_v + (size_t)m * HIDX + n)
                    = make_float2(tfr(h0), tfr(h1));
            else if (n < 2 * HIDX)
                *reinterpret_cast<float2*>(g_gate + (size_t)m * HIDX + (n - HIDX))
                    = make_float2(h0, h1);
            else
                *reinterpret_cast<float2*>(g_qksilu + (size_t)m * QKD + (n - 2 * HIDX))
                    = make_float2(h0, h1);
        } else {
            size_t off = (size_t)m * DIMX + n;
            float2 xr = *reinterpret_cast<const float2*>(xres + off);
            *reinterpret_cast<float2*>(out + off)
                = make_float2(v0 + bias1[n] + xr.x, v1 + bias1[n + 1] + xr.y);
        }
    }
}

// ================= attention GEMMs (tf32, 256 thr, 32x64 warp tiles) =========
// MODE 2: sim = qq@qkT /256 +bias, relu^2, mask   M=256b  N=256  K=128
// MODE 3: linkv = lkT@v /256                      M=128b  N=2048 K=256
// MODE 4: [attn|lq]@[v;linkvc], * gate -> acth    M=256b  N=2048 K=384
constexpr int KDIM[5] = {0, 0, 128, 256, 384};

#define A_BUF   (128 * ASTRIDE)
#define B_BUF_N (32 * BSTRIDE)
#define SMEMB_N ((2 * A_BUF + 2 * B_BUF_N) * 4)

template<int MODE>
__device__ __forceinline__ const float* a_ptr(int bg, int m, int k) {
    if constexpr (MODE == 2) return g_qq + ((size_t)bg * GQ + m) * QKD + k;
    else if constexpr (MODE == 3) return g_lkT + (size_t)bg * QKD * GQ + (size_t)m * GQ + k;
    else {
        if (k < GQ) return g_attn + (size_t)bg * GQ * GQ + (size_t)m * GQ + k;
        else        return g_lq + ((size_t)bg * GQ + m) * QKD + (k - GQ);
    }
}
template<int MODE>
__device__ __forceinline__ const float* bnm_ptr(int bg, int k, int n) {
    if constexpr (MODE == 2) return g_qkT + (size_t)bg * QKD * GQ + (size_t)k * GQ + n;
    else if constexpr (MODE == 3) return g_v + ((size_t)bg * GQ + k) * HIDX + n;
    else {
        if (k < GQ) return g_v + ((size_t)bg * GQ + k) * HIDX + n;
        else        return g_linkvc + (size_t)bg * QKD * HIDX + (size_t)(k - GQ) * HIDX + n;
    }
}

template<int MODE>
__global__ void __launch_bounds__(256) gemm_kernel() {
    constexpr int K  = KDIM[MODE];
    constexpr int KT = K / 32;
    extern __shared__ float smem[];
    float* As = smem;                 // [2][128][ASTRIDE]
    float* Bs = smem + 2 * A_BUF;     // [2][32][BSTRIDE]

    const int tid = threadIdx.x;
    int bx = blockIdx.x, by = blockIdx.y;
    if constexpr (MODE == 2) {        // lower-triangular blocks only: (0,0),(1,0),(1,1)
        int t = blockIdx.x;
        bx = (t + 1) >> 1;
        by = t >> 1;
    }
    const int m0 = bx * 128;
    const int n0 = by * 128;
    const int bg = blockIdx.z;
    const int warp = tid >> 5, lane = tid & 31;
    const int wm = warp & 3, wn = warp >> 2;
    const int gid = lane >> 2, tig = lane & 3;
    const int lm = lane >> 2, ln = (lane & 3) << 1;

    uint32_t sA = (uint32_t)__cvta_generic_to_shared(As);
    uint32_t sB = (uint32_t)__cvta_generic_to_shared(Bs);

    float acc[2][8][4];
    #pragma unroll
    for (int a = 0; a < 2; a++)
        #pragma unroll
        for (int b = 0; b < 8; b++)
            #pragma unroll
            for (int c = 0; c < 4; c++) acc[a][b][c] = 0.f;

    auto load_tile = [&](int kt, int buf) {
        int k0 = kt * 32;
        #pragma unroll
        for (int it = 0; it < 4; it++) {
            int idx = tid + it * 256;
            int r = idx >> 3, kc = (idx & 7) << 2;
            const float* gp = a_ptr<MODE>(bg, m0 + r, k0 + kc);
            uint32_t sa = sA + ((buf * 128 + r) * ASTRIDE + kc) * 4;
            asm volatile("cp.async.cg.shared.global [%0], [%1], 16;\n" :: "r"(sa), "l"(gp));
        }
        #pragma unroll
        for (int it = 0; it < 4; it++) {
            int idx = tid + it * 256;
            int r = idx >> 5, nc = (idx & 31) << 2;
            const float* gp = bnm_ptr<MODE>(bg, k0 + r, n0 + nc);
            uint32_t sb = sB + ((buf * 32 + r) * BSTRIDE + nc) * 4;
            asm volatile("cp.async.cg.shared.global [%0], [%1], 16;\n" :: "r"(sb), "l"(gp));
        }
        asm volatile("cp.async.commit_group;\n");
    };

    load_tile(0, 0);
    for (int kt = 0; kt < KT; kt++) {
        int cur = kt & 1;
        if (kt + 1 < KT) {
            load_tile(kt + 1, cur ^ 1);
            asm volatile("cp.async.wait_group 1;\n");
        } else {
            asm volatile("cp.async.wait_group 0;\n");
        }
        __syncthreads();
        #pragma unroll
        for (int ks = 0; ks < 32; ks += 8) {
            uint32_t af[2][4], bfr[8][2];
            #pragma unroll
            for (int mf = 0; mf < 2; mf++) {
                const float* ab = As + (cur * 128 + wm * 32 + mf * 16 + gid) * ASTRIDE + ks + 2 * tig;
                uint2 l0 = *reinterpret_cast<const uint2*>(ab);
                uint2 l1 = *reinterpret_cast<const uint2*>(ab + 8 * ASTRIDE);
                af[mf][0] = l0.x; af[mf][1] = l1.x; af[mf][2] = l0.y; af[mf][3] = l1.y;
            }
            #pragma unroll
            for (int nt = 0; nt < 8; nt++) {
                const uint32_t* bb = reinterpret_cast<const uint32_t*>(
                    Bs + (cur * 32 + ks + 2 * tig) * BSTRIDE + wn * 64 + nt * 8 + gid);
                bfr[nt][0] = bb[0];
                bfr[nt][1] = bb[BSTRIDE];
            }
            #pragma unroll
            for (int mf = 0; mf < 2; mf++)
                #pragma unroll
                for (int nf = 0; nf < 8; nf++)
                    mma_tf32(acc[mf][nf], af[mf], bfr[nf][0], bfr[nf][1]);
        }
        __syncthreads();
    }

    #pragma unroll
    for (int mf = 0; mf < 2; mf++)
    #pragma unroll
    for (int nf = 0; nf < 8; nf++)
    #pragma unroll
    for (int h = 0; h < 2; h++) {
        int m = m0 + wm * 32 + mf * 16 + lm + h * 8;
        int n = n0 + wn * 64 + nf * 8 + ln;
        float v0 = acc[mf][nf][h * 2 + 0];
        float v1 = acc[mf][nf][h * 2 + 1];
        if constexpr (MODE == 2) {
            float a0 = 0.f, a1 = 0.f;
            if (n <= m)     { float s = v0 * (1.f/256.f) + g_biastab[m - n];     s = fmaxf(s, 0.f); a0 = s * s; }
            if (n + 1 <= m) { float s = v1 * (1.f/256.f) + g_biastab[m - n - 1]; s = fmaxf(s, 0.f); a1 = s * s; }
            *reinterpret_cast<float2*>(g_attn + (size_t)bg * GQ * GQ + (size_t)m * GQ + n)
                = make_float2(tfr(a0), tfr(a1));
        } else if constexpr (MODE == 3) {
            *reinterpret_cast<float2*>(g_linkv + (size_t)bg * QKD * HIDX + (size_t)m * HIDX + n)
                = make_float2(v0 * (1.f/256.f), v1 * (1.f/256.f));
        } else {
            size_t row = (size_t)(bg * GQ + m);
            float2 gt = *reinterpret_cast<const float2*>(g_gate + row * HIDX + n);
            *reinterpret_cast<__half2*>(g_acth + row * HIDX + n)
                = __floats2half2_rn(v0 * gt.x, v1 * gt.y);
        }
    }
}

// ---------------- host launcher ----------------
extern "C" void kernel_launch(void* const* d_in, const int* in_sizes, int n_in,
                              void* d_out, int out_size) {
    const float* x         = (const float*)d_in[0];
    const float* ln_w      = (const float*)d_in[1];
    const float* ln_b      = (const float*)d_in[2];
    const float* Wh        = (const float*)d_in[3];
    const float* bh        = (const float*)d_in[4];
    const float* Wqk       = (const float*)d_in[5];
    const float* bqk       = (const float*)d_in[6];
    const float* qk_w      = (const float*)d_in[7];
    const float* qk_b      = (const float*)d_in[8];
    const float* rel_table = (const float*)d_in[9];
    const float* Wout      = (const float*)d_in[10];
    const float* bout      = (const float*)d_in[11];
    float* out = (float*)d_out;

    cudaFuncSetAttribute(wgemm<0>, cudaFuncAttributeMaxDynamicSharedMemorySize, W_SMEM);
    cudaFuncSetAttribute(wgemm<1>, cudaFuncAttributeMaxDynamicSharedMemorySize, W_SMEM);
    cudaFuncSetAttribute(gemm_kernel<2>, cudaFuncAttributeMaxDynamicSharedMemorySize, SMEMB_N);
    cudaFuncSetAttribute(gemm_kernel<3>, cudaFuncAttributeMaxDynamicSharedMemorySize, SMEMB_N);
    cudaFuncSetAttribute(gemm_kernel<4>, cudaFuncAttributeMaxDynamicSharedMemorySize, SMEMB_N);

    __half* WcatT_p; cudaGetSymbolAddress((void**)&WcatT_p, g_WcatTh);
    __half* WoutT_p; cudaGetSymbolAddress((void**)&WoutT_p, g_WoutTh);

    prep_kernel<<<1, 256>>>(rel_table);
    transpose_kernel<<<dim3(128, 32), dim3(32, 8)>>>(Wh,   WcatT_p,                       DIMX, 2 * HIDX);
    transpose_kernel<<<dim3(4, 32),   dim3(32, 8)>>>(Wqk,  WcatT_p + (size_t)4096 * DIMX, DIMX, QKD);
    transpose_kernel<<<dim3(32, 64),  dim3(32, 8)>>>(Wout, WoutT_p,                       HIDX, DIMX);
    ln_kernel<<<NTOK, 256>>>(x, ln_w, ln_b);
    wgemm<0><<<dim3(128, 33), 128, W_SMEM>>>(bh, bqk, nullptr, nullptr);
    qkhead_kernel<<<dim3(64, 4), dim3(32, 32)>>>(qk_w, qk_b);
    gemm_kernel<2><<<dim3(3, 1, 64),  256, SMEMB_N>>>();
    gemm_kernel<3><<<dim3(1, 16, 64), 256, SMEMB_N>>>();
    cumsum_kernel<<<4096, 256>>>();
    gemm_kernel<4><<<dim3(2, 16, 64), 256, SMEMB_N>>>();
    wgemm<1><<<dim3(128, 8), 128, W_SMEM>>>(bout, nullptr, x, out);
}

// round 13
// speedup vs baseline: 1.7405x; 1.1096x over previous
#include <cuda_runtime.h>
#include <cuda_fp16.h>
#include <cstdint>
#include <math.h>

#define DIMX  1024
#define GQ    256
#define QKD   128
#define HIDX  2048
#define NTOK  16384
#define NBG   64

// ---------------- scratch (device globals; no allocation) ----------------
__device__ __half g_normedh[(size_t)NTOK * DIMX];
__device__ __half g_vh   [(size_t)NTOK * HIDX];
__device__ float  g_gate [(size_t)NTOK * HIDX];
__device__ float  g_qksilu[(size_t)NTOK * QKD];
__device__ __half g_qqh  [(size_t)NTOK * QKD];
__device__ __half g_lqh  [(size_t)NTOK * QKD];
__device__ __half g_qkTh [(size_t)NBG * QKD * GQ];
__device__ __half g_lkTh [(size_t)NBG * QKD * GQ];
__device__ __half g_attnh[(size_t)NBG * GQ * GQ];
__device__ float  g_linkv[(size_t)NBG * QKD * HIDX];
__device__ __half g_linkvch[(size_t)NBG * QKD * HIDX];
__device__ __half g_acth [(size_t)NTOK * HIDX];
__device__ float  g_biastab[GQ];
// fp16, K-major (transposed) weights
__device__ __half g_WcatTh[(size_t)(2 * HIDX + QKD) * DIMX];  // [4224][1024]
__device__ __half g_WoutTh[(size_t)DIMX * HIDX];              // [1024][2048]

// ---------------- small helpers ----------------
__device__ __forceinline__ float silu_f(float x) { return x / (1.0f + expf(-x)); }

__device__ __forceinline__ void mma_f16(float (&d)[4], const uint32_t (&a)[4],
                                        uint32_t b0, uint32_t b1) {
    asm volatile(
        "mma.sync.aligned.m16n8k16.row.col.f32.f16.f16.f32 "
        "{%0,%1,%2,%3}, {%4,%5,%6,%7}, {%8,%9}, {%0,%1,%2,%3};\n"
        : "+f"(d[0]), "+f"(d[1]), "+f"(d[2]), "+f"(d[3])
        : "r"(a[0]), "r"(a[1]), "r"(a[2]), "r"(a[3]), "r"(b0), "r"(b1));
}
__device__ __forceinline__ void ldsm4(uint32_t (&r)[4], uint32_t a) {
    asm volatile("ldmatrix.sync.aligned.m8n8.x4.shared.b16 {%0,%1,%2,%3}, [%4];\n"
                 : "=r"(r[0]), "=r"(r[1]), "=r"(r[2]), "=r"(r[3]) : "r"(a));
}
__device__ __forceinline__ void ldsm4t(uint32_t (&r)[4], uint32_t a) {
    asm volatile("ldmatrix.sync.aligned.m8n8.x4.trans.shared.b16 {%0,%1,%2,%3}, [%4];\n"
                 : "=r"(r[0]), "=r"(r[1]), "=r"(r[2]), "=r"(r[3]) : "r"(a));
}

// ---------------- prep: T5 bias table ----------------
__global__ void prep_kernel(const float* __restrict__ rel_table) {
    int n = threadIdx.x;   // causal distance 0..255
    int bucket;
    if (n < 16) bucket = n;
    else {
        int v = 16 + (int)(logf((float)n / 16.0f) / logf(8.0f) * 16.0f);
        bucket = v < 31 ? v : 31;
    }
    g_biastab[n] = rel_table[bucket] * sqrtf(128.0f);
}

// ---------------- transpose + fp16 round: src[R][C] -> dst[C][R] ----------------
__global__ void transpose_kernel(const float* __restrict__ src, __half* __restrict__ dst,
                                 int R, int C) {
    __shared__ float t[32][33];
    int c0 = blockIdx.x * 32, r0 = blockIdx.y * 32;
    int tx = threadIdx.x, ty = threadIdx.y;   // 32 x 8
    #pragma unroll
    for (int j = 0; j < 32; j += 8)
        t[ty + j][tx] = src[(size_t)(r0 + ty + j) * C + c0 + tx];
    __syncthreads();
    #pragma unroll
    for (int j = 0; j < 32; j += 8)
        dst[(size_t)(c0 + ty + j) * R + r0 + tx] = __float2half_rn(t[tx][ty + j]);
}

// ---------------- LayerNorm -> fp16 ----------------
__global__ void ln_kernel(const float* __restrict__ x, const float* __restrict__ w,
                          const float* __restrict__ b) {
    int row = blockIdx.x, t = threadIdx.x;   // 256 threads, 4 floats each
    float4 f = reinterpret_cast<const float4*>(x + (size_t)row * DIMX)[t];
    float s  = f.x + f.y + f.z + f.w;
    float s2 = f.x*f.x + f.y*f.y + f.z*f.z + f.w*f.w;
    #pragma unroll
    for (int o = 16; o; o >>= 1) {
        s  += __shfl_xor_sync(0xffffffffu, s,  o);
        s2 += __shfl_xor_sync(0xffffffffu, s2, o);
    }
    __shared__ float ss[8], ss2[8], smu, sinv;
    if ((t & 31) == 0) { ss[t >> 5] = s; ss2[t >> 5] = s2; }
    __syncthreads();
    if (t == 0) {
        float S = 0.f, S2 = 0.f;
        #pragma unroll
        for (int k = 0; k < 8; k++) { S += ss[k]; S2 += ss2[k]; }
        float mu  = S * (1.0f / 1024.0f);
        float var = S2 * (1.0f / 1024.0f) - mu * mu;
        smu = mu; sinv = rsqrtf(var + 1e-5f);
    }
    __syncthreads();
    float mu = smu, inv = sinv;
    float4 wv = reinterpret_cast<const float4*>(w)[t];
    float4 bv = reinterpret_cast<const float4*>(b)[t];
    __half2* o2 = reinterpret_cast<__half2*>(g_normedh + (size_t)row * DIMX + t * 4);
    o2[0] = __floats2half2_rn((f.x - mu)*inv*wv.x + bv.x, (f.y - mu)*inv*wv.y + bv.y);
    o2[1] = __floats2half2_rn((f.z - mu)*inv*wv.z + bv.z, (f.w - mu)*inv*wv.w + bv.w);
}

// ---------------- head expand: coalesced smem transpose for k heads ----------
__global__ void qkhead_kernel(const float* __restrict__ qk_w, const float* __restrict__ qk_b) {
    __shared__ float s2[32][33], s3[32][33];
    int bg = blockIdx.x, d0 = blockIdx.y * 32;
    int tx = threadIdx.x, ty = threadIdx.y;
    int d = d0 + tx;
    float w0 = qk_w[d],           b0 = qk_b[d];
    float w1 = qk_w[QKD + d],     b1 = qk_b[QKD + d];
    float w2 = qk_w[2*QKD + d],   b2 = qk_b[2*QKD + d];
    float w3 = qk_w[3*QKD + d],   b3 = qk_b[3*QKD + d];
    #pragma unroll 1
    for (int tc = 0; tc < 8; tc++) {
        int tok = tc * 32 + ty;
        size_t t = (size_t)bg * GQ + tok;
        float v = g_qksilu[t * QKD + d];
        g_qqh[t * QKD + d] = __float2half_rn(v * w0 + b0);
        g_lqh[t * QKD + d] = __float2half_rn(v * w1 + b1);
        s2[tx][ty] = v * w2 + b2;
        s3[tx][ty] = v * w3 + b3;
        __syncthreads();
        size_t o = (size_t)bg * QKD * GQ + (size_t)(d0 + ty) * GQ + tc * 32 + tx;
        g_qkTh[o] = __float2half_rn(s2[ty][tx]);
        g_lkTh[o] = __float2half_rn(s3[ty][tx]);
        __syncthreads();
    }
}

// ---------------- exclusive cumsum over groups ----------------
__global__ void cumsum_kernel() {
    int i  = blockIdx.x * 256 + threadIdx.x;
    int b  = i >> 18;
    int de = i & ((1 << 18) - 1);
    float a = 0.f;
    #pragma unroll
    for (int g = 0; g < 16; g++) {
        size_t off = ((size_t)(b * 16 + g) << 18) + de;
        g_linkvch[off] = __float2half_rn(a);
        a += g_linkv[off];
    }
}

#define HSTR    80      // wgemm half stride (160B rows)

// ================= fp16 weight GEMMs: 128x128 CTA, 64x64 warp tiles, 128 thr =
// W=0: normedh @ WcatTh'  M=16384 N=4224 K=1024
// W=1: acth @ WoutTh'     M=16384 N=1024 K=2048
#define WH_BUF  (128 * HSTR)
#define W_SMEM  (4 * WH_BUF * 2)

template<int W>
__global__ void __launch_bounds__(128) wgemm(const float* __restrict__ bias1,
                                             const float* __restrict__ bias2,
                                             const float* __restrict__ xres,
                                             float* __restrict__ out) {
    constexpr int K  = W ? 2048 : 1024;
    constexpr int KT = K / 64;
    const __half* A = W ? g_acth : g_normedh;
    const __half* B = W ? g_WoutTh : g_WcatTh;

    extern __shared__ __half smemh[];
    __half* As = smemh;                  // [2][128][HSTR]
    __half* Bs = smemh + 2 * WH_BUF;     // [2][128][HSTR]
    uint32_t sA = (uint32_t)__cvta_generic_to_shared(As);
    uint32_t sB = (uint32_t)__cvta_generic_to_shared(Bs);

    const int tid = threadIdx.x;
    const int m0 = blockIdx.x * 128, n0 = blockIdx.y * 128;
    const int warp = tid >> 5, lane = tid & 31;
    const int wm = warp >> 1, wn = warp & 1;           // 2x2 warps -> 64x64 each
    const int gid = lane >> 2, tig = lane & 3;
    const int lm = lane >> 2, ln = (lane & 3) << 1;

    float acc[4][8][4];
    #pragma unroll
    for (int a = 0; a < 4; a++)
        #pragma unroll
        for (int b = 0; b < 8; b++)
            #pragma unroll
            for (int c = 0; c < 4; c++) acc[a][b][c] = 0.f;

    auto load_tile = [&](int kt, int buf) {
        int k0 = kt * 64;
        const __half* Ab = A + (size_t)m0 * K + k0;
        const __half* Bb = B + (size_t)n0 * K + k0;
        #pragma unroll
        for (int it = 0; it < 8; it++) {
            int idx = tid + it * 128;
            int r = idx >> 3, c = (idx & 7) << 3;
            uint32_t sa = sA + ((buf * 128 + r) * HSTR + c) * 2;
            asm volatile("cp.async.cg.shared.global [%0], [%1], 16;\n"
                         :: "r"(sa), "l"(Ab + (size_t)r * K + c));
        }
        #pragma unroll
        for (int it = 0; it < 8; it++) {
            int idx = tid + it * 128;
            int r = idx >> 3, c = (idx & 7) << 3;
            uint32_t sb = sB + ((buf * 128 + r) * HSTR + c) * 2;
            asm volatile("cp.async.cg.shared.global [%0], [%1], 16;\n"
                         :: "r"(sb), "l"(Bb + (size_t)r * K + c));
        }
        asm volatile("cp.async.commit_group;\n");
    };

    load_tile(0, 0);
    for (int kt = 0; kt < KT; kt++) {
        int cur = kt & 1;
        if (kt + 1 < KT) {
            load_tile(kt + 1, cur ^ 1);
            asm volatile("cp.async.wait_group 1;\n");
        } else {
            asm volatile("cp.async.wait_group 0;\n");
        }
        __syncthreads();
        // k16-permutation: logical k {2t,2t+1,2t+8,2t+9} -> phys {4t..4t+3}
        #pragma unroll
        for (int ks = 0; ks < 4; ks++) {
            uint32_t af[4][4], bfr[8][2];
            #pragma unroll
            for (int mf = 0; mf < 4; mf++) {
                const __half* ab = As + (size_t)(cur * 128 + wm * 64 + mf * 16 + gid) * HSTR
                                   + ks * 16 + 4 * tig;
                uint2 l0 = *reinterpret_cast<const uint2*>(ab);
                uint2 l1 = *reinterpret_cast<const uint2*>(ab + 8 * HSTR);
                af[mf][0] = l0.x; af[mf][1] = l1.x; af[mf][2] = l0.y; af[mf][3] = l1.y;
            }
            #pragma unroll
            for (int nt = 0; nt < 8; nt++) {
                const __half* bb = Bs + (size_t)(cur * 128 + wn * 64 + nt * 8 + gid) * HSTR
                                   + ks * 16 + 4 * tig;
                uint2 b2 = *reinterpret_cast<const uint2*>(bb);
                bfr[nt][0] = b2.x; bfr[nt][1] = b2.y;
            }
            #pragma unroll
            for (int mf = 0; mf < 4; mf++)
                #pragma unroll
                for (int nf = 0; nf < 8; nf++)
                    mma_f16(acc[mf][nf], af[mf], bfr[nf][0], bfr[nf][1]);
        }
        __syncthreads();
    }

    // -------- epilogue --------
    #pragma unroll
    for (int mf = 0; mf < 4; mf++)
    #pragma unroll
    for (int nf = 0; nf < 8; nf++)
    #pragma unroll
    for (int h = 0; h < 2; h++) {
        int m = m0 + wm * 64 + mf * 16 + lm + h * 8;
        int n = n0 + wn * 64 + nf * 8 + ln;
        float v0 = acc[mf][nf][h * 2 + 0];
        float v1 = acc[mf][nf][h * 2 + 1];
        if constexpr (W == 0) {
            float b0 = (n < 4096) ? bias1[n] : bias2[n - 4096];
            float b1 = (n < 4096) ? bias1[n + 1] : bias2[n - 4095];
            float h0 = silu_f(v0 + b0);
            float h1 = silu_f(v1 + b1);
            if (n < HIDX)
                *reinterpret_cast<__half2*>(g_vh + (size_t)m * HIDX + n)
                    = __floats2half2_rn(h0, h1);
            else if (n < 2 * HIDX)
                *reinterpret_cast<float2*>(g_gate + (size_t)m * HIDX + (n - HIDX))
                    = make_float2(h0, h1);
            else
                *reinterpret_cast<float2*>(g_qksilu + (size_t)m * QKD + (n - 2 * HIDX))
                    = make_float2(h0, h1);
        } else {
            size_t off = (size_t)m * DIMX + n;
            float2 xr = *reinterpret_cast<const float2*>(xres + off);
            *reinterpret_cast<float2*>(out + off)
                = make_float2(v0 + bias1[n] + xr.x, v1 + bias1[n + 1] + xr.y);
        }
    }
}

// ================= fp16 attention GEMMs (ldmatrix), 256 thr, 32x64 warp tiles
// MODE 2: sim = qq@qkT /256 +bias, relu^2, mask -> attnh   M=256b N=256  K=128
// MODE 3: linkv = lkT@v /256                               M=128b N=2048 K=256
// MODE 4: [attn|lq]@[v;linkvc], * gate -> acth             M=256b N=2048 K=384
constexpr int KDIM[5] = {0, 0, 128, 256, 384};

#define AH_STR  40      // A smem stride halves (80B = 5x16B, ldmatrix conflict-free)
#define BH_STR  136     // B smem stride halves (272B = 17x16B, conflict-free)
#define AH_BUF  (128 * AH_STR)
#define BH_BUF  (32 * BH_STR)
#define ASMEM_H ((2 * AH_BUF + 2 * BH_BUF) * 2)

template<int MODE>
__device__ __forceinline__ const __half* a_ptr(int bg, int m, int k) {
    if constexpr (MODE == 2) return g_qqh + ((size_t)bg * GQ + m) * QKD + k;
    else if constexpr (MODE == 3) return g_lkTh + (size_t)bg * QKD * GQ + (size_t)m * GQ + k;
    else {
        if (k < GQ) return g_attnh + (size_t)bg * GQ * GQ + (size_t)m * GQ + k;
        else        return g_lqh + ((size_t)bg * GQ + m) * QKD + (k - GQ);
    }
}
template<int MODE>
__device__ __forceinline__ const __half* bnm_ptr(int bg, int k, int n) {
    if constexpr (MODE == 2) return g_qkTh + (size_t)bg * QKD * GQ + (size_t)k * GQ + n;
    else if constexpr (MODE == 3) return g_vh + ((size_t)bg * GQ + k) * HIDX + n;
    else {
        if (k < GQ) return g_vh + ((size_t)bg * GQ + k) * HIDX + n;
        else        return g_linkvch + (size_t)bg * QKD * HIDX + (size_t)(k - GQ) * HIDX + n;
    }
}

template<int MODE>
__global__ void __launch_bounds__(256) gemm_kernel() {
    constexpr int K  = KDIM[MODE];
    constexpr int KT = K / 32;
    extern __shared__ __half smemh[];
    __half* As = smemh;                 // [2][128][AH_STR]
    __half* Bs = smemh + 2 * AH_BUF;    // [2][32][BH_STR]

    const int tid = threadIdx.x;
    int bx = blockIdx.x, by = blockIdx.y;
    if constexpr (MODE == 2) {        // lower-triangular blocks only: (0,0),(1,0),(1,1)
        int t = blockIdx.x;
        bx = (t + 1) >> 1;
        by = t >> 1;
    }
    const int m0 = bx * 128;
    const int n0 = by * 128;
    const int bg = blockIdx.z;
    const int warp = tid >> 5, lane = tid & 31;
    const int wm = warp & 3, wn = warp >> 2;           // 4x2 warps -> 32x64 each
    const int lr = lane & 15, lc = (lane >> 4) << 3;   // ldmatrix addressing
    const int lm = lane >> 2, ln = (lane & 3) << 1;

    uint32_t sA = (uint32_t)__cvta_generic_to_shared(As);
    uint32_t sB = (uint32_t)__cvta_generic_to_shared(Bs);

    float acc[2][8][4];
    #pragma unroll
    for (int a = 0; a < 2; a++)
        #pragma unroll
        for (int b = 0; b < 8; b++)
            #pragma unroll
            for (int c = 0; c < 4; c++) acc[a][b][c] = 0.f;

    auto load_tile = [&](int kt, int buf) {
        int k0 = kt * 32;
        #pragma unroll
        for (int it = 0; it < 2; it++) {               // A: 128 rows x 32 halves (4x16B/row)
            int idx = tid + it * 256;
            int r = idx >> 2, kc = (idx & 3) << 3;
            const __half* gp = a_ptr<MODE>(bg, m0 + r, k0 + kc);
            uint32_t sa = sA + ((buf * 128 + r) * AH_STR + kc) * 2;
            asm volatile("cp.async.cg.shared.global [%0], [%1], 16;\n" :: "r"(sa), "l"(gp));
        }
        #pragma unroll
        for (int it = 0; it < 2; it++) {               // B: 32 rows x 128 halves (16x16B/row)
            int idx = tid + it * 256;
            int r = idx >> 4, nc = (idx & 15) << 3;
            const __half* gp = bnm_ptr<MODE>(bg, k0 + r, n0 + nc);
            uint32_t sb = sB + ((buf * 32 + r) * BH_STR + nc) * 2;
            asm volatile("cp.async.cg.shared.global [%0], [%1], 16;\n" :: "r"(sb), "l"(gp));
        }
        asm volatile("cp.async.commit_group;\n");
    };

    load_tile(0, 0);
    for (int kt = 0; kt < KT; kt++) {
        int cur = kt & 1;
        if (kt + 1 < KT) {
            load_tile(kt + 1, cur ^ 1);
            asm volatile("cp.async.wait_group 1;\n");
        } else {
            asm volatile("cp.async.wait_group 0;\n");
        }
        __syncthreads();
        #pragma unroll
        for (int ks = 0; ks < 32; ks += 16) {
            uint32_t af[2][4], bfr[4][4];
            #pragma unroll
            for (int mf = 0; mf < 2; mf++) {
                uint32_t addr = sA + (((cur << 7) + wm * 32 + mf * 16 + lr) * AH_STR + ks + lc) * 2;
                ldsm4(af[mf], addr);
            }
            #pragma unroll
            for (int nt = 0; nt < 4; nt++) {
                uint32_t addr = sB + (((cur << 5) + ks + lr) * BH_STR + wn * 64 + nt * 16 + lc) * 2;
                ldsm4t(bfr[nt], addr);
            }
            #pragma unroll
            for (int mf = 0; mf < 2; mf++)
                #pragma unroll
                for (int nf = 0; nf < 8; nf++)
                    mma_f16(acc[mf][nf], af[mf],
                            bfr[nf >> 1][(nf & 1) << 1], bfr[nf >> 1][((nf & 1) << 1) + 1]);
        }
        __syncthreads();
    }

    #pragma unroll
    for (int mf = 0; mf < 2; mf++)
    #pragma unroll
    for (int nf = 0; nf < 8; nf++)
    #pragma unroll
    for (int h = 0; h < 2; h++) {
        int m = m0 + wm * 32 + mf * 16 + lm + h * 8;
        int n = n0 + wn * 64 + nf * 8 + ln;
        float v0 = acc[mf][nf][h * 2 + 0];
        float v1 = acc[mf][nf][h * 2 + 1];
        if constexpr (MODE == 2) {
            float a0 = 0.f, a1 = 0.f;
            if (n <= m)     { float s = v0 * (1.f/256.f) + g_biastab[m - n];     s = fmaxf(s, 0.f); a0 = s * s; }
            if (n + 1 <= m) { float s = v1 * (1.f/256.f) + g_biastab[m - n - 1]; s = fmaxf(s, 0.f); a1 = s * s; }
            *reinterpret_cast<__half2*>(g_attnh + (size_t)bg * GQ * GQ + (size_t)m * GQ + n)
                = __floats2half2_rn(a0, a1);
        } else if constexpr (MODE == 3) {
            *reinterpret_cast<float2*>(g_linkv + (size_t)bg * QKD * HIDX + (size_t)m * HIDX + n)
                = make_float2(v0 * (1.f/256.f), v1 * (1.f/256.f));
        } else {
            size_t row = (size_t)(bg * GQ + m);
            float2 gt = *reinterpret_cast<const float2*>(g_gate + row * HIDX + n);
            *reinterpret_cast<__half2*>(g_acth + row * HIDX + n)
                = __floats2half2_rn(v0 * gt.x, v1 * gt.y);
        }
    }
}

// ---------------- host launcher ----------------
extern "C" void kernel_launch(void* const* d_in, const int* in_sizes, int n_in,
                              void* d_out, int out_size) {
    const float* x         = (const float*)d_in[0];
    const float* ln_w      = (const float*)d_in[1];
    const float* ln_b      = (const float*)d_in[2];
    const float* Wh        = (const float*)d_in[3];
    const float* bh        = (const float*)d_in[4];
    const float* Wqk       = (const float*)d_in[5];
    const float* bqk       = (const float*)d_in[6];
    const float* qk_w      = (const float*)d_in[7];
    const float* qk_b      = (const float*)d_in[8];
    const float* rel_table = (const float*)d_in[9];
    const float* Wout      = (const float*)d_in[10];
    const float* bout      = (const float*)d_in[11];
    float* out = (float*)d_out;

    cudaFuncSetAttribute(wgemm<0>, cudaFuncAttributeMaxDynamicSharedMemorySize, W_SMEM);
    cudaFuncSetAttribute(wgemm<1>, cudaFuncAttributeMaxDynamicSharedMemorySize, W_SMEM);
    cudaFuncSetAttribute(gemm_kernel<2>, cudaFuncAttributeMaxDynamicSharedMemorySize, ASMEM_H);
    cudaFuncSetAttribute(gemm_kernel<3>, cudaFuncAttributeMaxDynamicSharedMemorySize, ASMEM_H);
    cudaFuncSetAttribute(gemm_kernel<4>, cudaFuncAttributeMaxDynamicSharedMemorySize, ASMEM_H);

    __half* WcatT_p; cudaGetSymbolAddress((void**)&WcatT_p, g_WcatTh);
    __half* WoutT_p; cudaGetSymbolAddress((void**)&WoutT_p, g_WoutTh);

    prep_kernel<<<1, 256>>>(rel_table);
    transpose_kernel<<<dim3(128, 32), dim3(32, 8)>>>(Wh,   WcatT_p,                       DIMX, 2 * HIDX);
    transpose_kernel<<<dim3(4, 32),   dim3(32, 8)>>>(Wqk,  WcatT_p + (size_t)4096 * DIMX, DIMX, QKD);
    transpose_kernel<<<dim3(32, 64),  dim3(32, 8)>>>(Wout, WoutT_p,                       HIDX, DIMX);
    ln_kernel<<<NTOK, 256>>>(x, ln_w, ln_b);
    wgemm<0><<<dim3(128, 33), 128, W_SMEM>>>(bh, bqk, nullptr, nullptr);
    qkhead_kernel<<<dim3(64, 4), dim3(32, 32)>>>(qk_w, qk_b);
    gemm_kernel<2><<<dim3(3, 1, 64),  256, ASMEM_H>>>();
    gemm_kernel<3><<<dim3(1, 16, 64), 256, ASMEM_H>>>();
    cumsum_kernel<<<4096, 256>>>();
    gemm_kernel<4><<<dim3(2, 16, 64), 256, ASMEM_H>>>();
    wgemm<1><<<dim3(128, 8), 128, W_SMEM>>>(bout, nullptr, x, out);
}

// round 14
// speedup vs baseline: 1.7555x; 1.0086x over previous
#include <cuda_runtime.h>
#include <cuda_fp16.h>
#include <cstdint>
#include <math.h>

#define DIMX  1024
#define GQ    256
#define QKD   128
#define HIDX  2048
#define NTOK  16384
#define NBG   64

// ---------------- scratch (device globals; no allocation) ----------------
__device__ __half g_normedh[(size_t)NTOK * DIMX];
__device__ __half g_vh   [(size_t)NTOK * HIDX];
__device__ float  g_gate [(size_t)NTOK * HIDX];
__device__ __half g_qksiluh[(size_t)NTOK * QKD];
__device__ __half g_qqh  [(size_t)NTOK * QKD];
__device__ __half g_lqh  [(size_t)NTOK * QKD];
__device__ __half g_qkTh [(size_t)NBG * QKD * GQ];
__device__ __half g_lkTh [(size_t)NBG * QKD * GQ];
__device__ __half g_attnh[(size_t)NBG * GQ * GQ];
__device__ __half g_linkvh[(size_t)NBG * QKD * HIDX];
__device__ __half g_linkvch[(size_t)NBG * QKD * HIDX];
__device__ __half g_acth [(size_t)NTOK * HIDX];
__device__ float  g_biastab[GQ];
// fp16, K-major (transposed) weights
__device__ __half g_WcatTh[(size_t)(2 * HIDX + QKD) * DIMX];  // [4224][1024]
__device__ __half g_WoutTh[(size_t)DIMX * HIDX];              // [1024][2048]

// ---------------- small helpers ----------------
__device__ __forceinline__ float silu_f(float x) { return x / (1.0f + expf(-x)); }

__device__ __forceinline__ void mma_f16(float (&d)[4], const uint32_t (&a)[4],
                                        uint32_t b0, uint32_t b1) {
    asm volatile(
        "mma.sync.aligned.m16n8k16.row.col.f32.f16.f16.f32 "
        "{%0,%1,%2,%3}, {%4,%5,%6,%7}, {%8,%9}, {%0,%1,%2,%3};\n"
        : "+f"(d[0]), "+f"(d[1]), "+f"(d[2]), "+f"(d[3])
        : "r"(a[0]), "r"(a[1]), "r"(a[2]), "r"(a[3]), "r"(b0), "r"(b1));
}
__device__ __forceinline__ void ldsm4(uint32_t (&r)[4], uint32_t a) {
    asm volatile("ldmatrix.sync.aligned.m8n8.x4.shared.b16 {%0,%1,%2,%3}, [%4];\n"
                 : "=r"(r[0]), "=r"(r[1]), "=r"(r[2]), "=r"(r[3]) : "r"(a));
}
__device__ __forceinline__ void ldsm4t(uint32_t (&r)[4], uint32_t a) {
    asm volatile("ldmatrix.sync.aligned.m8n8.x4.trans.shared.b16 {%0,%1,%2,%3}, [%4];\n"
                 : "=r"(r[0]), "=r"(r[1]), "=r"(r[2]), "=r"(r[3]) : "r"(a));
}

// ---------------- prep: T5 bias table ----------------
__global__ void prep_kernel(const float* __restrict__ rel_table) {
    int n = threadIdx.x;   // causal distance 0..255
    int bucket;
    if (n < 16) bucket = n;
    else {
        int v = 16 + (int)(logf((float)n / 16.0f) / logf(8.0f) * 16.0f);
        bucket = v < 31 ? v : 31;
    }
    g_biastab[n] = rel_table[bucket] * sqrtf(128.0f);
}

// ---------------- fused transpose of all 3 weights (one launch) -------------
// job0: Wh   [1024,4096] -> WcatTh rows 0..4095      (4096 tiles: 128 x 32)
// job1: Wqk  [1024,128]  -> WcatTh rows 4096..4223   (128 tiles: 4 x 32)
// job2: Wout [2048,1024] -> WoutTh                   (2048 tiles: 32 x 64)
__global__ void transpose_all_kernel(const float* __restrict__ Wh,
                                     const float* __restrict__ Wqk,
                                     const float* __restrict__ Wout) {
    __shared__ float t[32][33];
    int bid = blockIdx.x;
    const float* src; __half* dst; int R, C, bx, by;
    if (bid < 4096)      { src = Wh;   dst = g_WcatTh; R = DIMX; C = 2 * HIDX;
                           bx = bid & 127; by = bid >> 7; }
    else if (bid < 4224) { int u = bid - 4096; src = Wqk; dst = g_WcatTh + (size_t)4096 * DIMX;
                           R = DIMX; C = QKD; bx = u & 3; by = u >> 2; }
    else                 { int u = bid - 4224; src = Wout; dst = g_WoutTh; R = HIDX; C = DIMX;
                           bx = u & 31; by = u >> 5; }
    int c0 = bx * 32, r0 = by * 32;
    int tx = threadIdx.x, ty = threadIdx.y;   // 32 x 8
    #pragma unroll
    for (int j = 0; j < 32; j += 8)
        t[ty + j][tx] = src[(size_t)(r0 + ty + j) * C + c0 + tx];
    __syncthreads();
    #pragma unroll
    for (int j = 0; j < 32; j += 8)
        dst[(size_t)(c0 + ty + j) * R + r0 + tx] = __float2half_rn(t[tx][ty + j]);
}

// ---------------- LayerNorm -> fp16 ----------------
__global__ void ln_kernel(const float* __restrict__ x, const float* __restrict__ w,
                          const float* __restrict__ b) {
    int row = blockIdx.x, t = threadIdx.x;   // 256 threads, 4 floats each
    float4 f = reinterpret_cast<const float4*>(x + (size_t)row * DIMX)[t];
    float s  = f.x + f.y + f.z + f.w;
    float s2 = f.x*f.x + f.y*f.y + f.z*f.z + f.w*f.w;
    #pragma unroll
    for (int o = 16; o; o >>= 1) {
        s  += __shfl_xor_sync(0xffffffffu, s,  o);
        s2 += __shfl_xor_sync(0xffffffffu, s2, o);
    }
    __shared__ float ss[8], ss2[8], smu, sinv;
    if ((t & 31) == 0) { ss[t >> 5] = s; ss2[t >> 5] = s2; }
    __syncthreads();
    if (t == 0) {
        float S = 0.f, S2 = 0.f;
        #pragma unroll
        for (int k = 0; k < 8; k++) { S += ss[k]; S2 += ss2[k]; }
        float mu  = S * (1.0f / 1024.0f);
        float var = S2 * (1.0f / 1024.0f) - mu * mu;
        smu = mu; sinv = rsqrtf(var + 1e-5f);
    }
    __syncthreads();
    float mu = smu, inv = sinv;
    float4 wv = reinterpret_cast<const float4*>(w)[t];
    float4 bv = reinterpret_cast<const float4*>(b)[t];
    __half2* o2 = reinterpret_cast<__half2*>(g_normedh + (size_t)row * DIMX + t * 4);
    o2[0] = __floats2half2_rn((f.x - mu)*inv*wv.x + bv.x, (f.y - mu)*inv*wv.y + bv.y);
    o2[1] = __floats2half2_rn((f.z - mu)*inv*wv.z + bv.z, (f.w - mu)*inv*wv.w + bv.w);
}

// ---------------- head expand: coalesced smem transpose for k heads ----------
__global__ void qkhead_kernel(const float* __restrict__ qk_w, const float* __restrict__ qk_b) {
    __shared__ float s2[32][33], s3[32][33];
    int bg = blockIdx.x, d0 = blockIdx.y * 32;
    int tx = threadIdx.x, ty = threadIdx.y;
    int d = d0 + tx;
    float w0 = qk_w[d],           b0 = qk_b[d];
    float w1 = qk_w[QKD + d],     b1 = qk_b[QKD + d];
    float w2 = qk_w[2*QKD + d],   b2 = qk_b[2*QKD + d];
    float w3 = qk_w[3*QKD + d],   b3 = qk_b[3*QKD + d];
    #pragma unroll 1
    for (int tc = 0; tc < 8; tc++) {
        int tok = tc * 32 + ty;
        size_t t = (size_t)bg * GQ + tok;
        float v = __half2float(g_qksiluh[t * QKD + d]);
        g_qqh[t * QKD + d] = __float2half_rn(v * w0 + b0);
        g_lqh[t * QKD + d] = __float2half_rn(v * w1 + b1);
        s2[tx][ty] = v * w2 + b2;
        s3[tx][ty] = v * w3 + b3;
        __syncthreads();
        size_t o = (size_t)bg * QKD * GQ + (size_t)(d0 + ty) * GQ + tc * 32 + tx;
        g_qkTh[o] = __float2half_rn(s2[ty][tx]);
        g_lkTh[o] = __float2half_rn(s3[ty][tx]);
        __syncthreads();
    }
}

// ---------------- exclusive cumsum over groups (half in/out, fp32 accum) -----
__global__ void cumsum_kernel() {
    int i  = blockIdx.x * 256 + threadIdx.x;
    int b  = i >> 18;
    int de = i & ((1 << 18) - 1);
    float a = 0.f;
    #pragma unroll
    for (int g = 0; g < 16; g++) {
        size_t off = ((size_t)(b * 16 + g) << 18) + de;
        g_linkvch[off] = __float2half_rn(a);
        a += __half2float(g_linkvh[off]);
    }
}

#define HSTR    80      // wgemm half stride (160B rows)

// ================= fp16 weight GEMMs: 128x128 CTA, 64x64 warp tiles, 128 thr =
// W=0: normedh @ WcatTh'  M=16384 N=4224 K=1024
// W=1: acth @ WoutTh'     M=16384 N=1024 K=2048
#define WH_BUF  (128 * HSTR)
#define W_SMEM  (4 * WH_BUF * 2)

template<int W>
__global__ void __launch_bounds__(128) wgemm(const float* __restrict__ bias1,
                                             const float* __restrict__ bias2,
                                             const float* __restrict__ xres,
                                             float* __restrict__ out) {
    constexpr int K  = W ? 2048 : 1024;
    constexpr int KT = K / 64;
    const __half* A = W ? g_acth : g_normedh;
    const __half* B = W ? g_WoutTh : g_WcatTh;

    extern __shared__ __half smemh[];
    __half* As = smemh;                  // [2][128][HSTR]
    __half* Bs = smemh + 2 * WH_BUF;     // [2][128][HSTR]
    uint32_t sA = (uint32_t)__cvta_generic_to_shared(As);
    uint32_t sB = (uint32_t)__cvta_generic_to_shared(Bs);

    const int tid = threadIdx.x;
    const int m0 = blockIdx.x * 128, n0 = blockIdx.y * 128;
    const int warp = tid >> 5, lane = tid & 31;
    const int wm = warp >> 1, wn = warp & 1;           // 2x2 warps -> 64x64 each
    const int gid = lane >> 2, tig = lane & 3;
    const int lm = lane >> 2, ln = (lane & 3) << 1;

    float acc[4][8][4];
    #pragma unroll
    for (int a = 0; a < 4; a++)
        #pragma unroll
        for (int b = 0; b < 8; b++)
            #pragma unroll
            for (int c = 0; c < 4; c++) acc[a][b][c] = 0.f;

    auto load_tile = [&](int kt, int buf) {
        int k0 = kt * 64;
        const __half* Ab = A + (size_t)m0 * K + k0;
        const __half* Bb = B + (size_t)n0 * K + k0;
        #pragma unroll
        for (int it = 0; it < 8; it++) {
            int idx = tid + it * 128;
            int r = idx >> 3, c = (idx & 7) << 3;
            uint32_t sa = sA + ((buf * 128 + r) * HSTR + c) * 2;
            asm volatile("cp.async.cg.shared.global [%0], [%1], 16;\n"
                         :: "r"(sa), "l"(Ab + (size_t)r * K + c));
        }
        #pragma unroll
        for (int it = 0; it < 8; it++) {
            int idx = tid + it * 128;
            int r = idx >> 3, c = (idx & 7) << 3;
            uint32_t sb = sB + ((buf * 128 + r) * HSTR + c) * 2;
            asm volatile("cp.async.cg.shared.global [%0], [%1], 16;\n"
                         :: "r"(sb), "l"(Bb + (size_t)r * K + c));
        }
        asm volatile("cp.async.commit_group;\n");
    };

    load_tile(0, 0);
    for (int kt = 0; kt < KT; kt++) {
        int cur = kt & 1;
        if (kt + 1 < KT) {
            load_tile(kt + 1, cur ^ 1);
            asm volatile("cp.async.wait_group 1;\n");
        } else {
            asm volatile("cp.async.wait_group 0;\n");
        }
        __syncthreads();
        // k16-permutation: logical k {2t,2t+1,2t+8,2t+9} -> phys {4t..4t+3}
        #pragma unroll
        for (int ks = 0; ks < 4; ks++) {
            uint32_t af[4][4], bfr[8][2];
            #pragma unroll
            for (int mf = 0; mf < 4; mf++) {
                const __half* ab = As + (size_t)(cur * 128 + wm * 64 + mf * 16 + gid) * HSTR
                                   + ks * 16 + 4 * tig;
                uint2 l0 = *reinterpret_cast<const uint2*>(ab);
                uint2 l1 = *reinterpret_cast<const uint2*>(ab + 8 * HSTR);
                af[mf][0] = l0.x; af[mf][1] = l1.x; af[mf][2] = l0.y; af[mf][3] = l1.y;
            }
            #pragma unroll
            for (int nt = 0; nt < 8; nt++) {
                const __half* bb = Bs + (size_t)(cur * 128 + wn * 64 + nt * 8 + gid) * HSTR
                                   + ks * 16 + 4 * tig;
                uint2 b2 = *reinterpret_cast<const uint2*>(bb);
                bfr[nt][0] = b2.x; bfr[nt][1] = b2.y;
            }
            #pragma unroll
            for (int mf = 0; mf < 4; mf++)
                #pragma unroll
                for (int nf = 0; nf < 8; nf++)
                    mma_f16(acc[mf][nf], af[mf], bfr[nf][0], bfr[nf][1]);
        }
        __syncthreads();
    }

    // -------- epilogue --------
    #pragma unroll
    for (int mf = 0; mf < 4; mf++)
    #pragma unroll
    for (int nf = 0; nf < 8; nf++)
    #pragma unroll
    for (int h = 0; h < 2; h++) {
        int m = m0 + wm * 64 + mf * 16 + lm + h * 8;
        int n = n0 + wn * 64 + nf * 8 + ln;
        float v0 = acc[mf][nf][h * 2 + 0];
        float v1 = acc[mf][nf][h * 2 + 1];
        if constexpr (W == 0) {
            float b0 = (n < 4096) ? bias1[n] : bias2[n - 4096];
            float b1 = (n < 4096) ? bias1[n + 1] : bias2[n - 4095];
            float h0 = silu_f(v0 + b0);
            float h1 = silu_f(v1 + b1);
            if (n < HIDX)
                *reinterpret_cast<__half2*>(g_vh + (size_t)m * HIDX + n)
                    = __floats2half2_rn(h0, h1);
            else if (n < 2 * HIDX)
                *reinterpret_cast<float2*>(g_gate + (size_t)m * HIDX + (n - HIDX))
                    = make_float2(h0, h1);
            else
                *reinterpret_cast<__half2*>(g_qksiluh + (size_t)m * QKD + (n - 2 * HIDX))
                    = __floats2half2_rn(h0, h1);
        } else {
            size_t off = (size_t)m * DIMX + n;
            float2 xr = *reinterpret_cast<const float2*>(xres + off);
            *reinterpret_cast<float2*>(out + off)
                = make_float2(v0 + bias1[n] + xr.x, v1 + bias1[n + 1] + xr.y);
        }
    }
}

// ================= fp16 attention GEMMs (ldmatrix), 256 thr, 32x64 warp tiles
// MODE 2: sim = qq@qkT /256 +bias, relu^2, mask -> attnh   M=256b N=256  K=128
// MODE 3: linkv = lkT@v /256 -> linkvh                     M=128b N=2048 K=256
// MODE 4: [attn|lq]@[v;linkvc], * gate -> acth             M=256b N=2048 K=384
constexpr int KDIM[5] = {0, 0, 128, 256, 384};

#define AH_STR  40      // A smem stride halves (80B = 5x16B, ldmatrix conflict-free)
#define BH_STR  136     // B smem stride halves (272B = 17x16B, conflict-free)
#define AH_BUF  (128 * AH_STR)
#define BH_BUF  (32 * BH_STR)
#define ASMEM_H ((2 * AH_BUF + 2 * BH_BUF) * 2)

template<int MODE>
__device__ __forceinline__ const __half* a_ptr(int bg, int m, int k) {
    if constexpr (MODE == 2) return g_qqh + ((size_t)bg * GQ + m) * QKD + k;
    else if constexpr (MODE == 3) return g_lkTh + (size_t)bg * QKD * GQ + (size_t)m * GQ + k;
    else {
        if (k < GQ) return g_attnh + (size_t)bg * GQ * GQ + (size_t)m * GQ + k;
        else        return g_lqh + ((size_t)bg * GQ + m) * QKD + (k - GQ);
    }
}
template<int MODE>
__device__ __forceinline__ const __half* bnm_ptr(int bg, int k, int n) {
    if constexpr (MODE == 2) return g_qkTh + (size_t)bg * QKD * GQ + (size_t)k * GQ + n;
    else if constexpr (MODE == 3) return g_vh + ((size_t)bg * GQ + k) * HIDX + n;
    else {
        if (k < GQ) return g_vh + ((size_t)bg * GQ + k) * HIDX + n;
        else        return g_linkvch + (size_t)bg * QKD * HIDX + (size_t)(k - GQ) * HIDX + n;
    }
}

template<int MODE>
__global__ void __launch_bounds__(256) gemm_kernel() {
    constexpr int K  = KDIM[MODE];
    constexpr int KT = K / 32;
    extern __shared__ __half smemh[];
    __half* As = smemh;                 // [2][128][AH_STR]
    __half* Bs = smemh + 2 * AH_BUF;    // [2][32][BH_STR]

    const int tid = threadIdx.x;
    int bx = blockIdx.x, by = blockIdx.y;
    if constexpr (MODE == 2) {        // lower-triangular blocks only: (0,0),(1,0),(1,1)
        int t = blockIdx.x;
        bx = (t + 1) >> 1;
        by = t >> 1;
    }
    const int m0 = bx * 128;
    const int n0 = by * 128;
    const int bg = blockIdx.z;
    const int warp = tid >> 5, lane = tid & 31;
    const int wm = warp & 3, wn = warp >> 2;           // 4x2 warps -> 32x64 each
    const int lr = lane & 15, lc = (lane >> 4) << 3;   // ldmatrix addressing
    const int lm = lane >> 2, ln = (lane & 3) << 1;

    uint32_t sA = (uint32_t)__cvta_generic_to_shared(As);
    uint32_t sB = (uint32_t)__cvta_generic_to_shared(Bs);

    float acc[2][8][4];
    #pragma unroll
    for (int a = 0; a < 2; a++)
        #pragma unroll
        for (int b = 0; b < 8; b++)
            #pragma unroll
            for (int c = 0; c < 4; c++) acc[a][b][c] = 0.f;

    auto load_tile = [&](int kt, int buf) {
        int k0 = kt * 32;
        #pragma unroll
        for (int it = 0; it < 2; it++) {               // A: 128 rows x 32 halves
            int idx = tid + it * 256;
            int r = idx >> 2, kc = (idx & 3) << 3;
            const __half* gp = a_ptr<MODE>(bg, m0 + r, k0 + kc);
            uint32_t sa = sA + ((buf * 128 + r) * AH_STR + kc) * 2;
            asm volatile("cp.async.cg.shared.global [%0], [%1], 16;\n" :: "r"(sa), "l"(gp));
        }
        #pragma unroll
        for (int it = 0; it < 2; it++) {               // B: 32 rows x 128 halves
            int idx = tid + it * 256;
            int r = idx >> 4, nc = (idx & 15) << 3;
            const __half* gp = bnm_ptr<MODE>(bg, k0 + r, n0 + nc);
            uint32_t sb = sB + ((buf * 32 + r) * BH_STR + nc) * 2;
            asm volatile("cp.async.cg.shared.global [%0], [%1], 16;\n" :: "r"(sb), "l"(gp));
        }
        asm volatile("cp.async.commit_group;\n");
    };

    load_tile(0, 0);
    for (int kt = 0; kt < KT; kt++) {
        int cur = kt & 1;
        if (kt + 1 < KT) {
            load_tile(kt + 1, cur ^ 1);
            asm volatile("cp.async.wait_group 1;\n");
        } else {
            asm volatile("cp.async.wait_group 0;\n");
        }
        __syncthreads();
        #pragma unroll
        for (int ks = 0; ks < 32; ks += 16) {
            uint32_t af[2][4], bfr[4][4];
            #pragma unroll
            for (int mf = 0; mf < 2; mf++) {
                uint32_t addr = sA + (((cur << 7) + wm * 32 + mf * 16 + lr) * AH_STR + ks + lc) * 2;
                ldsm4(af[mf], addr);
            }
            #pragma unroll
            for (int nt = 0; nt < 4; nt++) {
                uint32_t addr = sB + (((cur << 5) + ks + lr) * BH_STR + wn * 64 + nt * 16 + lc) * 2;
                ldsm4t(bfr[nt], addr);
            }
            #pragma unroll
            for (int mf = 0; mf < 2; mf++)
                #pragma unroll
                for (int nf = 0; nf < 8; nf++)
                    mma_f16(acc[mf][nf], af[mf],
                            bfr[nf >> 1][(nf & 1) << 1], bfr[nf >> 1][((nf & 1) << 1) + 1]);
        }
        __syncthreads();
    }

    #pragma unroll
    for (int mf = 0; mf < 2; mf++)
    #pragma unroll
    for (int nf = 0; nf < 8; nf++)
    #pragma unroll
    for (int h = 0; h < 2; h++) {
        int m = m0 + wm * 32 + mf * 16 + lm + h * 8;
        int n = n0 + wn * 64 + nf * 8 + ln;
        float v0 = acc[mf][nf][h * 2 + 0];
        float v1 = acc[mf][nf][h * 2 + 1];
        if constexpr (MODE == 2) {
            float a0 = 0.f, a1 = 0.f;
            if (n <= m)     { float s = v0 * (1.f/256.f) + g_biastab[m - n];     s = fmaxf(s, 0.f); a0 = s * s; }
            if (n + 1 <= m) { float s = v1 * (1.f/256.f) + g_biastab[m - n - 1]; s = fmaxf(s, 0.f); a1 = s * s; }
            *reinterpret_cast<__half2*>(g_attnh + (size_t)bg * GQ * GQ + (size_t)m * GQ + n)
                = __floats2half2_rn(a0, a1);
        } else if constexpr (MODE == 3) {
            *reinterpret_cast<__half2*>(g_linkvh + (size_t)bg * QKD * HIDX + (size_t)m * HIDX + n)
                = __floats2half2_rn(v0 * (1.f/256.f), v1 * (1.f/256.f));
        } else {
            size_t row = (size_t)(bg * GQ + m);
            float2 gt = *reinterpret_cast<const float2*>(g_gate + row * HIDX + n);
            *reinterpret_cast<__half2*>(g_acth + row * HIDX + n)
                = __floats2half2_rn(v0 * gt.x, v1 * gt.y);
        }
    }
}

// ---------------- host launcher ----------------
extern "C" void kernel_launch(void* const* d_in, const int* in_sizes, int n_in,
                              void* d_out, int out_size) {
    const float* x         = (const float*)d_in[0];
    const float* ln_w      = (const float*)d_in[1];
    const float* ln_b      = (const float*)d_in[2];
    const float* Wh        = (const float*)d_in[3];
    const float* bh        = (const float*)d_in[4];
    const float* Wqk       = (const float*)d_in[5];
    const float* bqk       = (const float*)d_in[6];
    const float* qk_w      = (const float*)d_in[7];
    const float* qk_b      = (const float*)d_in[8];
    const float* rel_table = (const float*)d_in[9];
    const float* Wout      = (const float*)d_in[10];
    const float* bout      = (const float*)d_in[11];
    float* out = (float*)d_out;

    cudaFuncSetAttribute(wgemm<0>, cudaFuncAttributeMaxDynamicSharedMemorySize, W_SMEM);
    cudaFuncSetAttribute(wgemm<1>, cudaFuncAttributeMaxDynamicSharedMemorySize, W_SMEM);
    cudaFuncSetAttribute(gemm_kernel<2>, cudaFuncAttributeMaxDynamicSharedMemorySize, ASMEM_H);
    cudaFuncSetAttribute(gemm_kernel<3>, cudaFuncAttributeMaxDynamicSharedMemorySize, ASMEM_H);
    cudaFuncSetAttribute(gemm_kernel<4>, cudaFuncAttributeMaxDynamicSharedMemorySize, ASMEM_H);

    prep_kernel<<<1, 256>>>(rel_table);
    transpose_all_kernel<<<6272, dim3(32, 8)>>>(Wh, Wqk, Wout);
    ln_kernel<<<NTOK, 256>>>(x, ln_w, ln_b);
    wgemm<0><<<dim3(128, 33), 128, W_SMEM>>>(bh, bqk, nullptr, nullptr);   // launch #3 (ncu)
    qkhead_kernel<<<dim3(64, 4), dim3(32, 32)>>>(qk_w, qk_b);
    gemm_kernel<2><<<dim3(3, 1, 64),  256, ASMEM_H>>>();
    gemm_kernel<3><<<dim3(1, 16, 64), 256, ASMEM_H>>>();
    cumsum_kernel<<<4096, 256>>>();
    gemm_kernel<4><<<dim3(2, 16, 64), 256, ASMEM_H>>>();
    wgemm<1><<<dim3(128, 8), 128, W_SMEM>>>(bout, nullptr, x, out);
}